// round 4
// baseline (speedup 1.0000x reference)
#include <cuda_runtime.h>
#include <math.h>

#define BB 4
#define NNODE 256
#define DIM 512
#define NH 8
#define KSP 25

// ---------------------------------------------------------------------------
// Scratch (no allocations allowed anywhere)
// ---------------------------------------------------------------------------
__device__ float g_cur [BB*NNODE*DIM];
__device__ float g_qkv [BB*NNODE*3*DIM];
__device__ float g_atto[BB*NNODE*DIM];
__device__ float g_lvl0[BB*NNODE*DIM];
__device__ float g_lvl1[BB*(NNODE/2)*DIM];
__device__ float g_lvl2[BB*(NNODE/4)*DIM];
__device__ float g_t1  [BB*NNODE*(DIM/2)];
__device__ float g_p   [BB*NNODE*DIM];
__device__ float g_cat [BB*NNODE*3*DIM];
__device__ float g_hier[BB*NNODE*DIM];
__device__ float g_ef  [BB*NNODE*2*DIM];
__device__ float g_wef [DIM*2*DIM];
__device__ float g_bef [2*DIM];
__device__ float g_sc  [BB*NNODE*NNODE];

typedef unsigned long long u64;

__device__ __forceinline__ void ffma2(u64& d, u64 a, u64 b) {
    asm("fma.rn.f32x2 %0, %1, %2, %0;" : "+l"(d) : "l"(a), "l"(b));
}
__device__ __forceinline__ void unpack2(u64 v, float& lo, float& hi) {
    asm("mov.b64 {%0, %1}, %2;" : "=f"(lo), "=f"(hi) : "l"(v));
}

// ---------------------------------------------------------------------------
// SGEMM: C[M,Nc] = A[M,K] @ W[K,Nc] (+bias) (+relu / pool)
// 64 threads, 64x64 tile, 8x8 per thread, BK=16, double-buffered.
// Accumulators are f32x2 pairs over M; B stored duplicated in shared so both
// FFMA2 operands load directly as 64-bit pairs (zero packing MOVs).
// mode: 0 = bias, 1 = bias+relu, 2 = pairwise-pool rows (0.5*(r0+r1)+bias)
// ---------------------------------------------------------------------------
__global__ void __launch_bounds__(64)
sgemm_k(const float* __restrict__ A, const float* __restrict__ W,
        const float* __restrict__ bias, float* __restrict__ C,
        int M, int K, int Nc, int mode)
{
    __shared__ float As[2][16][68];    // transposed A tile, padded
    __shared__ float Bs[2][16][128];   // duplicated B tile: Bs[k][2n],[2n+1] = b[n]

    const int bm = blockIdx.y * 64, bn = blockIdx.x * 64;
    const int tid = threadIdx.x;
    const int ty = tid >> 3;        // 0..7 : rows ty*8 .. ty*8+7
    const int tx = tid & 7;         // 0..7 : cols tx*8 .. tx*8+7

    u64 acc[4][8];
#pragma unroll
    for (int i = 0; i < 4; i++)
#pragma unroll
        for (int j = 0; j < 8; j++) acc[i][j] = 0ull;

    const int nk = K >> 4;
    const int ar = tid >> 2, ac = tid & 3;     // A: row ar+16i, float4 col ac
    const int bk = tid >> 4, bn4 = tid & 15;   // B: k row bk+4i, float4 col bn4

    float4 areg[4], breg[4];

#pragma unroll
    for (int i = 0; i < 4; i++)
        areg[i] = *(const float4*)&A[(size_t)(bm + i * 16 + ar) * K + ac * 4];
#pragma unroll
    for (int i = 0; i < 4; i++)
        breg[i] = *(const float4*)&W[(size_t)(i * 4 + bk) * Nc + bn + bn4 * 4];

#pragma unroll
    for (int i = 0; i < 4; i++) {
        int r = i * 16 + ar;
        As[0][ac * 4 + 0][r] = areg[i].x;
        As[0][ac * 4 + 1][r] = areg[i].y;
        As[0][ac * 4 + 2][r] = areg[i].z;
        As[0][ac * 4 + 3][r] = areg[i].w;
        int k = i * 4 + bk, nb = bn4 * 8;
        *(float2*)&Bs[0][k][nb + 0] = make_float2(breg[i].x, breg[i].x);
        *(float2*)&Bs[0][k][nb + 2] = make_float2(breg[i].y, breg[i].y);
        *(float2*)&Bs[0][k][nb + 4] = make_float2(breg[i].z, breg[i].z);
        *(float2*)&Bs[0][k][nb + 6] = make_float2(breg[i].w, breg[i].w);
    }
    __syncthreads();

    for (int k0 = 0; k0 < nk; k0++) {
        const int buf = k0 & 1;
        if (k0 + 1 < nk) {
            const int kb = (k0 + 1) << 4;
#pragma unroll
            for (int i = 0; i < 4; i++)
                areg[i] = *(const float4*)&A[(size_t)(bm + i * 16 + ar) * K + kb + ac * 4];
#pragma unroll
            for (int i = 0; i < 4; i++)
                breg[i] = *(const float4*)&W[(size_t)(kb + i * 4 + bk) * Nc + bn + bn4 * 4];
        }
#pragma unroll
        for (int kk = 0; kk < 16; kk++) {
            ulonglong2 aA = *(const ulonglong2*)&As[buf][kk][ty * 8];
            ulonglong2 aB = *(const ulonglong2*)&As[buf][kk][ty * 8 + 4];
            ulonglong2 b0 = *(const ulonglong2*)&Bs[buf][kk][tx * 16];
            ulonglong2 b1 = *(const ulonglong2*)&Bs[buf][kk][tx * 16 + 4];
            ulonglong2 b2 = *(const ulonglong2*)&Bs[buf][kk][tx * 16 + 8];
            ulonglong2 b3 = *(const ulonglong2*)&Bs[buf][kk][tx * 16 + 12];
            u64 bd[8] = {b0.x, b0.y, b1.x, b1.y, b2.x, b2.y, b3.x, b3.y};
#pragma unroll
            for (int n = 0; n < 8; n++) ffma2(acc[0][n], aA.x, bd[n]);
#pragma unroll
            for (int n = 0; n < 8; n++) ffma2(acc[1][n], aA.y, bd[n]);
#pragma unroll
            for (int n = 0; n < 8; n++) ffma2(acc[2][n], aB.x, bd[n]);
#pragma unroll
            for (int n = 0; n < 8; n++) ffma2(acc[3][n], aB.y, bd[n]);
        }
        if (k0 + 1 < nk) {
            const int nb2 = buf ^ 1;
#pragma unroll
            for (int i = 0; i < 4; i++) {
                int r = i * 16 + ar;
                As[nb2][ac * 4 + 0][r] = areg[i].x;
                As[nb2][ac * 4 + 1][r] = areg[i].y;
                As[nb2][ac * 4 + 2][r] = areg[i].z;
                As[nb2][ac * 4 + 3][r] = areg[i].w;
                int k = i * 4 + bk, nb = bn4 * 8;
                *(float2*)&Bs[nb2][k][nb + 0] = make_float2(breg[i].x, breg[i].x);
                *(float2*)&Bs[nb2][k][nb + 2] = make_float2(breg[i].y, breg[i].y);
                *(float2*)&Bs[nb2][k][nb + 4] = make_float2(breg[i].z, breg[i].z);
                *(float2*)&Bs[nb2][k][nb + 6] = make_float2(breg[i].w, breg[i].w);
            }
        }
        __syncthreads();
    }

    float4 bb0 = make_float4(0.f, 0.f, 0.f, 0.f);
    float4 bb1 = bb0;
    if (bias) {
        bb0 = *(const float4*)&bias[bn + tx * 8];
        bb1 = *(const float4*)&bias[bn + tx * 8 + 4];
    }
    const float bv[8] = {bb0.x, bb0.y, bb0.z, bb0.w, bb1.x, bb1.y, bb1.z, bb1.w};

    if (mode == 2) {
        // pairwise pool: output row = (global row pair)/2
#pragma unroll
        for (int mp = 0; mp < 4; mp++) {
            float lo[8], hi[8], v[8];
#pragma unroll
            for (int n = 0; n < 8; n++) {
                unpack2(acc[mp][n], lo[n], hi[n]);
                v[n] = 0.5f * (lo[n] + hi[n]) + bv[n];
            }
            int pr = (bm >> 1) + ty * 4 + mp;
            *(float4*)&C[(size_t)pr * Nc + bn + tx * 8]     = make_float4(v[0], v[1], v[2], v[3]);
            *(float4*)&C[(size_t)pr * Nc + bn + tx * 8 + 4] = make_float4(v[4], v[5], v[6], v[7]);
        }
    } else {
#pragma unroll
        for (int mp = 0; mp < 4; mp++) {
            float lo[8], hi[8];
#pragma unroll
            for (int n = 0; n < 8; n++) unpack2(acc[mp][n], lo[n], hi[n]);
#pragma unroll
            for (int h = 0; h < 2; h++) {
                const float* src = h ? hi : lo;
                float v[8];
#pragma unroll
                for (int n = 0; n < 8; n++) {
                    v[n] = src[n] + bv[n];
                    if (mode == 1) v[n] = fmaxf(v[n], 0.f);
                }
                int m = bm + ty * 8 + mp * 2 + h;
                *(float4*)&C[(size_t)m * Nc + bn + tx * 8]     = make_float4(v[0], v[1], v[2], v[3]);
                *(float4*)&C[(size_t)m * Nc + bn + tx * 8 + 4] = make_float4(v[4], v[5], v[6], v[7]);
            }
        }
    }
}

// ---------------------------------------------------------------------------
// Multi-head attention: qkv [B, Nl, 3*DIM] -> out [B, Nl, DIM]
// grid (B*NH, 4), block 256. K/V in shared (pitch 68), f32x2 QK dot,
// duplicated-probability AV phase.
// ---------------------------------------------------------------------------
__global__ void attn_k(const float* __restrict__ qkv, float* __restrict__ out, int Nl)
{
    extern __shared__ float sm[];
    float* Ks  = sm;                    // Nl*68
    float* Vs  = Ks + Nl * 68;          // Nl*68
    float* qs  = Vs + Nl * 68;          // 8*64
    float* psd = qs + 8 * 64;           // 8 * 2*Nl (duplicated probs)

    const int b = blockIdx.x >> 3, h = blockIdx.x & 7;
    const float* base = qkv + (size_t)b * Nl * (3 * DIM);
    const int tid = threadIdx.x, warp = tid >> 5, lane = tid & 31;

    for (int idx = tid; idx < Nl * 16; idx += 256) {
        int n = idx >> 4, dv = idx & 15;
        const float* rowp = base + (size_t)n * (3 * DIM) + h * 64 + dv * 4;
        *(float4*)&Ks[n * 68 + dv * 4] = *(const float4*)(rowp + DIM);
        *(float4*)&Vs[n * 68 + dv * 4] = *(const float4*)(rowp + 2 * DIM);
    }
    __syncthreads();

    const int jcnt = Nl >> 5;
    for (int r = blockIdx.y * 8 + warp; r < Nl; r += 8 * gridDim.y) {
        if (lane < 16)
            ((float4*)&qs[warp * 64])[lane] =
                *(const float4*)&base[(size_t)r * (3 * DIM) + h * 64 + lane * 4];
        __syncwarp();

        const ulonglong2* qr = (const ulonglong2*)&qs[warp * 64];
        float sv[8];
        float mx = -1e30f;
        for (int t = 0; t < jcnt; t++) {
            int j = t * 32 + lane;
            const ulonglong2* kr = (const ulonglong2*)&Ks[j * 68];
            u64 p0 = 0ull, p1 = 0ull;
#pragma unroll
            for (int i = 0; i < 16; i += 2) {
                ulonglong2 q0 = qr[i],     k0 = kr[i];
                ulonglong2 q1 = qr[i + 1], k1 = kr[i + 1];
                ffma2(p0, q0.x, k0.x); ffma2(p1, q0.y, k0.y);
                ffma2(p0, q1.x, k1.x); ffma2(p1, q1.y, k1.y);
            }
            float a0, a1, a2, a3;
            unpack2(p0, a0, a1); unpack2(p1, a2, a3);
            float s = (a0 + a1 + a2 + a3) * 0.125f;
            sv[t] = s;
            mx = fmaxf(mx, s);
        }
#pragma unroll
        for (int o = 16; o; o >>= 1) mx = fmaxf(mx, __shfl_xor_sync(0xffffffffu, mx, o));
        float sum = 0.f;
        for (int t = 0; t < jcnt; t++) { float e = expf(sv[t] - mx); sv[t] = e; sum += e; }
#pragma unroll
        for (int o = 16; o; o >>= 1) sum += __shfl_xor_sync(0xffffffffu, sum, o);
        float inv = 1.f / sum;
        for (int t = 0; t < jcnt; t++) {
            int j = t * 32 + lane;
            float p = sv[t] * inv;
            *(float2*)&psd[warp * 2 * Nl + 2 * j] = make_float2(p, p);
        }
        __syncwarp();

        // AV: each lane owns d = 2*lane, 2*lane+1
        u64 av[4] = {0ull, 0ull, 0ull, 0ull};
        const float* pw = &psd[warp * 2 * Nl];
        for (int j = 0; j < Nl; j += 4) {
            ffma2(av[0], *(const u64*)&pw[2 * j],     *(const u64*)&Vs[(j)     * 68 + 2 * lane]);
            ffma2(av[1], *(const u64*)&pw[2 * j + 2], *(const u64*)&Vs[(j + 1) * 68 + 2 * lane]);
            ffma2(av[2], *(const u64*)&pw[2 * j + 4], *(const u64*)&Vs[(j + 2) * 68 + 2 * lane]);
            ffma2(av[3], *(const u64*)&pw[2 * j + 6], *(const u64*)&Vs[(j + 3) * 68 + 2 * lane]);
        }
        float l0, h0, l1, h1, l2, h2, l3, h3;
        unpack2(av[0], l0, h0); unpack2(av[1], l1, h1);
        unpack2(av[2], l2, h2); unpack2(av[3], l3, h3);
        float e0 = (l0 + l1) + (l2 + l3);
        float e1 = (h0 + h1) + (h2 + h3);
        *(float2*)&out[((size_t)b * Nl + r) * DIM + h * 64 + 2 * lane] = make_float2(e0, e1);
        __syncwarp();
    }
}

// ---------------------------------------------------------------------------
// Upsample + concat (float4)
// ---------------------------------------------------------------------------
__global__ void concat_k(const float* __restrict__ l0, const float* __restrict__ l1,
                         const float* __restrict__ l2, float* __restrict__ cat)
{
    int idx4 = blockIdx.x * blockDim.x + threadIdx.x;
    const int total4 = BB * NNODE * 3 * DIM / 4;
    if (idx4 >= total4) return;
    int c4 = idx4 % (3 * DIM / 4);
    int n  = (idx4 / (3 * DIM / 4)) % NNODE;
    int b  = idx4 / ((3 * DIM / 4) * NNODE);
    int col = c4 * 4, l = col >> 9, d = col & 511;
    const float* src = (l == 0) ? l0 : (l == 1) ? l1 : l2;
    int Nl = NNODE >> l;
    ((float4*)cat)[idx4] = *(const float4*)&src[((size_t)b * Nl + (n >> l)) * DIM + d];
}

// ---------------------------------------------------------------------------
// LayerNorm over last dim (512)
// ---------------------------------------------------------------------------
__global__ void ln_k(const float* __restrict__ in, const float* __restrict__ g,
                     const float* __restrict__ bta, float* __restrict__ out)
{
    const int row = blockIdx.x, t = threadIdx.x;
    const int warp = t >> 5, lane = t & 31;
    float4 v = ((const float4*)(in + (size_t)row * DIM))[t];
    __shared__ float red[4];

    float s = v.x + v.y + v.z + v.w;
#pragma unroll
    for (int o = 16; o; o >>= 1) s += __shfl_xor_sync(0xffffffffu, s, o);
    if (lane == 0) red[warp] = s;
    __syncthreads();
    float mean = (red[0] + red[1] + red[2] + red[3]) * (1.f / DIM);
    __syncthreads();

    float dx = v.x - mean, dy = v.y - mean, dz = v.z - mean, dw = v.w - mean;
    float s2 = dx * dx + dy * dy + dz * dz + dw * dw;
#pragma unroll
    for (int o = 16; o; o >>= 1) s2 += __shfl_xor_sync(0xffffffffu, s2, o);
    if (lane == 0) red[warp] = s2;
    __syncthreads();
    float var = (red[0] + red[1] + red[2] + red[3]) * (1.f / DIM);
    float inv = 1.f / sqrtf(var + 1e-5f);

    float4 gv = ((const float4*)g)[t];
    float4 bv = ((const float4*)bta)[t];
    float4 r;
    r.x = dx * inv * gv.x + bv.x;
    r.y = dy * inv * gv.y + bv.y;
    r.z = dz * inv * gv.z + bv.z;
    r.w = dw * inv * gv.w + bv.w;
    ((float4*)(out + (size_t)row * DIM))[t] = r;
}

// ---------------------------------------------------------------------------
// Repack We1[1024,512] -> wef[512,1024] (hi|hj column blocks) + fused bias
// ---------------------------------------------------------------------------
__global__ void repack_k(const float* __restrict__ We1, const float* __restrict__ be1,
                         float* __restrict__ wef, float* __restrict__ bef)
{
    int idx = blockIdx.x * blockDim.x + threadIdx.x;
    if (idx < DIM * 2 * DIM) {
        int k = idx >> 10, n = idx & 1023;
        wef[idx] = (n < DIM) ? We1[(size_t)k * DIM + n]
                             : We1[(size_t)(DIM + k) * DIM + (n - DIM)];
    }
    if (idx < 2 * DIM) bef[idx] = (idx < DIM) ? 0.f : be1[idx - DIM];
}

// ---------------------------------------------------------------------------
// Edge scores from merged ef buffer (row stride 1024: [hi | hj]).
// sc[b,i,j] = sum_d relu(hi[i,d] + hj[j,d]) * w2[d]; diag -> -1e30
// 64x32 tile, 256 threads (4i x 2j per thread), grid (8,4,B)
// ---------------------------------------------------------------------------
__global__ void scores_k(const float* __restrict__ ef, const float* __restrict__ w2,
                         float* __restrict__ sc)
{
    __shared__ float His[16][68];
    __shared__ float Hjs[16][36];
    __shared__ float W2s[16];
    const int b = blockIdx.z;
    const int i0 = blockIdx.y * 64, j0 = blockIdx.x * 32;
    const int tid = threadIdx.x;
    const int tx = tid & 15, ty = tid >> 4;
    const float* hib = ef + ((size_t)b * NNODE + i0) * (2 * DIM);
    const float* hjb = ef + ((size_t)b * NNODE + j0) * (2 * DIM) + DIM;

    float acc[4][2];
#pragma unroll
    for (int i = 0; i < 4; i++) { acc[i][0] = 0.f; acc[i][1] = 0.f; }

    const int ir = tid >> 2, ic = tid & 3;     // His load: 64 rows x 4 float4
    const int jr = tid >> 3, jc = tid & 7;     // Hjs load: 32 rows x 8 float2

    for (int k0 = 0; k0 < DIM; k0 += 16) {
        float4 a = *(const float4*)&hib[(size_t)ir * (2 * DIM) + k0 + ic * 4];
        His[ic * 4 + 0][ir] = a.x; His[ic * 4 + 1][ir] = a.y;
        His[ic * 4 + 2][ir] = a.z; His[ic * 4 + 3][ir] = a.w;
        float2 c = *(const float2*)&hjb[(size_t)jr * (2 * DIM) + k0 + jc * 2];
        Hjs[jc * 2 + 0][jr] = c.x; Hjs[jc * 2 + 1][jr] = c.y;
        if (tid < 16) W2s[tid] = w2[k0 + tid];
        __syncthreads();
#pragma unroll
        for (int kk = 0; kk < 16; kk++) {
            float4 h4 = *(const float4*)&His[kk][ty * 4];
            float2 j2 = *(const float2*)&Hjs[kk][tx * 2];
            float w = W2s[kk];
            float hv[4] = {h4.x, h4.y, h4.z, h4.w};
#pragma unroll
            for (int i = 0; i < 4; i++) {
                acc[i][0] += fmaxf(hv[i] + j2.x, 0.f) * w;
                acc[i][1] += fmaxf(hv[i] + j2.y, 0.f) * w;
            }
        }
        __syncthreads();
    }

#pragma unroll
    for (int i = 0; i < 4; i++) {
        int gi = i0 + ty * 4 + i;
#pragma unroll
        for (int j = 0; j < 2; j++) {
            int gj = j0 + tx * 2 + j;
            sc[((size_t)b * NNODE + gi) * NNODE + gj] = (gi == gj) ? -1e30f : acc[i][j];
        }
    }
}

// ---------------------------------------------------------------------------
// Top-k (k=25) per row, warp per row; zeroes its row first.
// ---------------------------------------------------------------------------
__global__ void topk_k(const float* __restrict__ sc, float* __restrict__ adj)
{
    const int warp = threadIdx.x >> 5, lane = threadIdx.x & 31;
    const int row = blockIdx.x * 8 + warp;
    const float* s = sc + (size_t)row * NNODE;
    float v[8];
#pragma unroll
    for (int t = 0; t < 8; t++) v[t] = s[t * 32 + lane];
    float* arow = adj + (size_t)row * NNODE;
#pragma unroll
    for (int t = 0; t < 8; t++) arow[t * 32 + lane] = 0.f;
    __syncwarp();

    for (int it = 0; it < KSP; it++) {
        float bv = -3e38f; int bi = 0;
#pragma unroll
        for (int t = 0; t < 8; t++) {
            int j = t * 32 + lane;
            if (v[t] > bv) { bv = v[t]; bi = j; }
        }
#pragma unroll
        for (int o = 16; o; o >>= 1) {
            float ov = __shfl_xor_sync(0xffffffffu, bv, o);
            int   oi = __shfl_xor_sync(0xffffffffu, bi, o);
            if (ov > bv || (ov == bv && oi < bi)) { bv = ov; bi = oi; }
        }
        if (lane == (bi & 31)) v[bi >> 5] = -3e38f;
        if (lane == 0) arow[bi] = 1.0f;
        __syncwarp();
    }
}

// ---------------------------------------------------------------------------
// Host orchestration
// ---------------------------------------------------------------------------
static float* symaddr(const void* s)
{
    void* p = nullptr;
    cudaGetSymbolAddress(&p, s);
    return (float*)p;
}

extern "C" void kernel_launch(void* const* d_in, const int* in_sizes, int n_in,
                              void* d_out, int out_size)
{
    const float* x      = (const float*)d_in[0];
    const float* Wqkv   = (const float*)d_in[2];
    const float* bqkv   = (const float*)d_in[3];
    const float* Wo     = (const float*)d_in[4];
    const float* bo     = (const float*)d_in[5];
    const float* Wp1    = (const float*)d_in[6];
    const float* bp1    = (const float*)d_in[7];
    const float* Wp2    = (const float*)d_in[8];
    const float* bp2    = (const float*)d_in[9];
    const float* Wfuse  = (const float*)d_in[10];
    const float* bfuse  = (const float*)d_in[11];
    const float* ln_g   = (const float*)d_in[12];
    const float* ln_b   = (const float*)d_in[13];
    const float* We1    = (const float*)d_in[14];
    const float* be1    = (const float*)d_in[15];
    const float* We2    = (const float*)d_in[16];
    const float* Ws_qkv = (const float*)d_in[18];
    const float* bs_qkv = (const float*)d_in[19];
    const float* Ws_o   = (const float*)d_in[20];
    const float* bs_o   = (const float*)d_in[21];

    float* out_att = (float*)d_out;                      // [B,N,D]
    float* out_adj = out_att + (size_t)BB * NNODE * DIM; // [B,N,N]

    float* cur  = symaddr(g_cur);
    float* qkv  = symaddr(g_qkv);
    float* atto = symaddr(g_atto);
    float* lvl0 = symaddr(g_lvl0);
    float* lvl1 = symaddr(g_lvl1);
    float* lvl2 = symaddr(g_lvl2);
    float* t1   = symaddr(g_t1);
    float* pbuf = symaddr(g_p);
    float* cat  = symaddr(g_cat);
    float* hier = symaddr(g_hier);
    float* ef   = symaddr(g_ef);
    float* wef  = symaddr(g_wef);
    float* bef  = symaddr(g_bef);
    float* sc   = symaddr(g_sc);

    cudaFuncSetAttribute(attn_k, cudaFuncAttributeMaxDynamicSharedMemorySize, 160000);

    float* lvls[3] = {lvl0, lvl1, lvl2};
    const float* curp = x;

    // repack We1 early (independent of everything else)
    repack_k<<<(DIM * 2 * DIM + 255) / 256, 256>>>(We1, be1, wef, bef);

    for (int l = 0; l < 3; l++) {
        const int Nl = NNODE >> l;
        const int M  = BB * Nl;
        sgemm_k<<<dim3(3 * DIM / 64, M / 64), 64>>>(
            curp, Wqkv + (size_t)l * DIM * 3 * DIM, bqkv + (size_t)l * 3 * DIM,
            qkv, M, DIM, 3 * DIM, 0);
        size_t smem = (size_t)(Nl * 68 * 2 + 8 * 64 + 8 * 2 * Nl) * sizeof(float);
        attn_k<<<dim3(BB * NH, 4), 256, smem>>>(qkv, atto, Nl);
        sgemm_k<<<dim3(DIM / 64, M / 64), 64>>>(
            atto, Wo + (size_t)l * DIM * DIM, bo + (size_t)l * DIM,
            lvls[l], M, DIM, DIM, 0);
        if (l < 2) {
            sgemm_k<<<dim3(DIM / 2 / 64, M / 64), 64>>>(
                lvls[l], Wp1 + (size_t)l * DIM * (DIM / 2), bp1 + (size_t)l * (DIM / 2),
                t1, M, DIM, DIM / 2, 1);
            // Wp2 with fused pairwise pooling -> cur (M/2 rows)
            sgemm_k<<<dim3(DIM / 64, M / 64), 64>>>(
                t1, Wp2 + (size_t)l * (DIM / 2) * DIM, bp2 + (size_t)l * DIM,
                cur, M, DIM / 2, DIM, 2);
            curp = cur;
        }
    }

    // fuse: concat upsampled levels -> GEMM(relu) -> LayerNorm
    {
        const int total4 = BB * NNODE * 3 * DIM / 4;
        concat_k<<<(total4 + 255) / 256, 256>>>(lvl0, lvl1, lvl2, cat);
        sgemm_k<<<dim3(DIM / 64, BB * NNODE / 64), 64>>>(
            cat, Wfuse, bfuse, pbuf, BB * NNODE, 3 * DIM, DIM, 1);
        ln_k<<<BB * NNODE, 128>>>(pbuf, ln_g, ln_b, hier);
    }

    // sparse edge scoring + top-k (merged hi|hj GEMM)
    {
        sgemm_k<<<dim3(2 * DIM / 64, BB * NNODE / 64), 64>>>(
            hier, wef, bef, ef, BB * NNODE, DIM, 2 * DIM, 0);
        scores_k<<<dim3(NNODE / 32, NNODE / 64, BB), 256>>>(ef, We2, sc);
        topk_k<<<BB * NNODE / 8, 256>>>(sc, out_adj);
    }

    // final MHA on hier -> attended output
    {
        const int M = BB * NNODE;
        sgemm_k<<<dim3(3 * DIM / 64, M / 64), 64>>>(
            hier, Ws_qkv, bs_qkv, qkv, M, DIM, 3 * DIM, 0);
        size_t smem = (size_t)(NNODE * 68 * 2 + 8 * 64 + 8 * 2 * NNODE) * sizeof(float);
        attn_k<<<dim3(BB * NH, 4), 256, smem>>>(qkv, atto, NNODE);
        sgemm_k<<<dim3(DIM / 64, M / 64), 64>>>(
            atto, Ws_o, bs_o, out_att, M, DIM, DIM, 0);
    }
}

// round 5
// speedup vs baseline: 1.2796x; 1.2796x over previous
#include <cuda_runtime.h>
#include <math.h>

#define BB 4
#define NNODE 256
#define DIM 512
#define NH 8
#define KSP 25

// ---------------------------------------------------------------------------
// Scratch (no allocations allowed anywhere)
// ---------------------------------------------------------------------------
__device__ float g_cur [BB*NNODE*DIM];
__device__ float g_qkv [BB*NNODE*3*DIM];
__device__ float g_atto[BB*NNODE*DIM];
__device__ float g_lvl0[BB*NNODE*DIM];
__device__ float g_lvl1[BB*(NNODE/2)*DIM];
__device__ float g_lvl2[BB*(NNODE/4)*DIM];
__device__ float g_t1  [BB*NNODE*(DIM/2)];
__device__ float g_p   [BB*NNODE*DIM];
__device__ float g_cat [BB*NNODE*3*DIM];
__device__ float g_hier[BB*NNODE*DIM];
__device__ float g_ef  [BB*NNODE*2*DIM];
__device__ float g_wef [DIM*2*DIM];
__device__ float g_bef [2*DIM];
__device__ float g_sc  [BB*NNODE*NNODE];

typedef unsigned long long u64;

__device__ __forceinline__ void ffma2(u64& d, u64 a, u64 b) {
    asm("fma.rn.f32x2 %0, %1, %2, %0;" : "+l"(d) : "l"(a), "l"(b));
}
__device__ __forceinline__ void unpack2(u64 v, float& lo, float& hi) {
    asm("mov.b64 {%0, %1}, %2;" : "=f"(lo), "=f"(hi) : "l"(v));
}

// ---------------------------------------------------------------------------
// SGEMM: C[M,Nc] = A[M,K] @ W[K,Nc] (+bias) (+relu / pool)
// 128 threads (4 warps), 64x64 tile, 8Mx4N per thread, BK=16, double-buffered.
// Accumulators are f32x2 pairs over M; A pairs load directly from transposed
// As; B stored DUPLICATED in shared so (b,b) pairs load directly. Zero packing
// MOVs in the inner loop.
// mode: 0 = bias, 1 = bias+relu, 2 = pairwise-pool rows (0.5*(r0+r1)+bias)
// ---------------------------------------------------------------------------
__global__ void __launch_bounds__(128)
sgemm_k(const float* __restrict__ A, const float* __restrict__ W,
        const float* __restrict__ bias, float* __restrict__ C,
        int M, int K, int Nc, int mode)
{
    __shared__ float As[2][16][68];    // transposed A tile, padded
    __shared__ float Bs[2][16][128];   // duplicated B tile: Bs[k][2n],[2n+1] = b[n]

    const int bm = blockIdx.y * 64, bn = blockIdx.x * 64;
    const int tid = threadIdx.x;
    const int ty = tid >> 4;        // 0..7 : rows ty*8 .. ty*8+7
    const int tx = tid & 15;        // 0..15: cols tx*4 .. tx*4+3

    u64 acc[4][4];                  // [M-pair][n]
#pragma unroll
    for (int i = 0; i < 4; i++)
#pragma unroll
        for (int j = 0; j < 4; j++) acc[i][j] = 0ull;

    const int nk = K >> 4;
    // A loads: f = tid*2+i -> row f>>2 (0..63), float4 col f&3
    // B loads: f = tid*2+i -> k f>>4 (0..15), float4 col f&15
    float4 areg[2], breg[2];

#pragma unroll
    for (int i = 0; i < 2; i++) {
        int f = tid * 2 + i;
        areg[i] = *(const float4*)&A[(size_t)(bm + (f >> 2)) * K + (f & 3) * 4];
        breg[i] = *(const float4*)&W[(size_t)(f >> 4) * Nc + bn + (f & 15) * 4];
    }
#pragma unroll
    for (int i = 0; i < 2; i++) {
        int f = tid * 2 + i, r = f >> 2, c = f & 3;
        As[0][c * 4 + 0][r] = areg[i].x;
        As[0][c * 4 + 1][r] = areg[i].y;
        As[0][c * 4 + 2][r] = areg[i].z;
        As[0][c * 4 + 3][r] = areg[i].w;
        int k = f >> 4, nb = (f & 15) * 8;
        *(float2*)&Bs[0][k][nb + 0] = make_float2(breg[i].x, breg[i].x);
        *(float2*)&Bs[0][k][nb + 2] = make_float2(breg[i].y, breg[i].y);
        *(float2*)&Bs[0][k][nb + 4] = make_float2(breg[i].z, breg[i].z);
        *(float2*)&Bs[0][k][nb + 6] = make_float2(breg[i].w, breg[i].w);
    }
    __syncthreads();

    for (int k0 = 0; k0 < nk; k0++) {
        const int buf = k0 & 1;
        if (k0 + 1 < nk) {
            const int kb = (k0 + 1) << 4;
#pragma unroll
            for (int i = 0; i < 2; i++) {
                int f = tid * 2 + i;
                areg[i] = *(const float4*)&A[(size_t)(bm + (f >> 2)) * K + kb + (f & 3) * 4];
                breg[i] = *(const float4*)&W[(size_t)(kb + (f >> 4)) * Nc + bn + (f & 15) * 4];
            }
        }
#pragma unroll
        for (int kk = 0; kk < 16; kk++) {
            ulonglong2 aA = *(const ulonglong2*)&As[buf][kk][ty * 8];       // pairs 0,1
            ulonglong2 aB = *(const ulonglong2*)&As[buf][kk][ty * 8 + 4];   // pairs 2,3
            ulonglong2 b0 = *(const ulonglong2*)&Bs[buf][kk][tx * 8];       // n0,n1 dup
            ulonglong2 b1 = *(const ulonglong2*)&Bs[buf][kk][tx * 8 + 4];   // n2,n3 dup
            ffma2(acc[0][0], aA.x, b0.x); ffma2(acc[0][1], aA.x, b0.y);
            ffma2(acc[0][2], aA.x, b1.x); ffma2(acc[0][3], aA.x, b1.y);
            ffma2(acc[1][0], aA.y, b0.x); ffma2(acc[1][1], aA.y, b0.y);
            ffma2(acc[1][2], aA.y, b1.x); ffma2(acc[1][3], aA.y, b1.y);
            ffma2(acc[2][0], aB.x, b0.x); ffma2(acc[2][1], aB.x, b0.y);
            ffma2(acc[2][2], aB.x, b1.x); ffma2(acc[2][3], aB.x, b1.y);
            ffma2(acc[3][0], aB.y, b0.x); ffma2(acc[3][1], aB.y, b0.y);
            ffma2(acc[3][2], aB.y, b1.x); ffma2(acc[3][3], aB.y, b1.y);
        }
        if (k0 + 1 < nk) {
            const int nb2 = buf ^ 1;
#pragma unroll
            for (int i = 0; i < 2; i++) {
                int f = tid * 2 + i, r = f >> 2, c = f & 3;
                As[nb2][c * 4 + 0][r] = areg[i].x;
                As[nb2][c * 4 + 1][r] = areg[i].y;
                As[nb2][c * 4 + 2][r] = areg[i].z;
                As[nb2][c * 4 + 3][r] = areg[i].w;
                int k = f >> 4, nb = (f & 15) * 8;
                *(float2*)&Bs[nb2][k][nb + 0] = make_float2(breg[i].x, breg[i].x);
                *(float2*)&Bs[nb2][k][nb + 2] = make_float2(breg[i].y, breg[i].y);
                *(float2*)&Bs[nb2][k][nb + 4] = make_float2(breg[i].z, breg[i].z);
                *(float2*)&Bs[nb2][k][nb + 6] = make_float2(breg[i].w, breg[i].w);
            }
        }
        __syncthreads();
    }

    float4 bb = make_float4(0.f, 0.f, 0.f, 0.f);
    if (bias) bb = *(const float4*)&bias[bn + tx * 4];
    const float bv[4] = {bb.x, bb.y, bb.z, bb.w};

    if (mode == 2) {
        // pairwise pool: rows (2r,2r+1) -> pooled row; pair is in one acc
#pragma unroll
        for (int mp = 0; mp < 4; mp++) {
            float v[4];
#pragma unroll
            for (int n = 0; n < 4; n++) {
                float lo, hi;
                unpack2(acc[mp][n], lo, hi);
                v[n] = 0.5f * (lo + hi) + bv[n];
            }
            int pr = (bm >> 1) + ty * 4 + mp;
            *(float4*)&C[(size_t)pr * Nc + bn + tx * 4] = make_float4(v[0], v[1], v[2], v[3]);
        }
    } else {
#pragma unroll
        for (int mp = 0; mp < 4; mp++) {
            float lo[4], hi[4];
#pragma unroll
            for (int n = 0; n < 4; n++) unpack2(acc[mp][n], lo[n], hi[n]);
#pragma unroll
            for (int h = 0; h < 2; h++) {
                const float* src = h ? hi : lo;
                float v[4];
#pragma unroll
                for (int n = 0; n < 4; n++) {
                    v[n] = src[n] + bv[n];
                    if (mode == 1) v[n] = fmaxf(v[n], 0.f);
                }
                int m = bm + ty * 8 + mp * 2 + h;
                *(float4*)&C[(size_t)m * Nc + bn + tx * 4] = make_float4(v[0], v[1], v[2], v[3]);
            }
        }
    }
}

// ---------------------------------------------------------------------------
// Multi-head attention: qkv [B, Nl, 3*DIM] -> out [B, Nl, DIM]
// grid (B*NH, 4), block 256. K/V in shared (pitch 68), f32x2 QK dot,
// duplicated-probability AV phase.
// ---------------------------------------------------------------------------
__global__ void attn_k(const float* __restrict__ qkv, float* __restrict__ out, int Nl)
{
    extern __shared__ float sm[];
    float* Ks  = sm;                    // Nl*68
    float* Vs  = Ks + Nl * 68;          // Nl*68
    float* qs  = Vs + Nl * 68;          // 8*64
    float* psd = qs + 8 * 64;           // 8 * 2*Nl (duplicated probs)

    const int b = blockIdx.x >> 3, h = blockIdx.x & 7;
    const float* base = qkv + (size_t)b * Nl * (3 * DIM);
    const int tid = threadIdx.x, warp = tid >> 5, lane = tid & 31;

    for (int idx = tid; idx < Nl * 16; idx += 256) {
        int n = idx >> 4, dv = idx & 15;
        const float* rowp = base + (size_t)n * (3 * DIM) + h * 64 + dv * 4;
        *(float4*)&Ks[n * 68 + dv * 4] = *(const float4*)(rowp + DIM);
        *(float4*)&Vs[n * 68 + dv * 4] = *(const float4*)(rowp + 2 * DIM);
    }
    __syncthreads();

    const int jcnt = Nl >> 5;
    for (int r = blockIdx.y * 8 + warp; r < Nl; r += 8 * gridDim.y) {
        if (lane < 16)
            ((float4*)&qs[warp * 64])[lane] =
                *(const float4*)&base[(size_t)r * (3 * DIM) + h * 64 + lane * 4];
        __syncwarp();

        const ulonglong2* qr = (const ulonglong2*)&qs[warp * 64];
        float sv[8];
        float mx = -1e30f;
        for (int t = 0; t < jcnt; t++) {
            int j = t * 32 + lane;
            const ulonglong2* kr = (const ulonglong2*)&Ks[j * 68];
            u64 p0 = 0ull, p1 = 0ull;
#pragma unroll
            for (int i = 0; i < 16; i += 2) {
                ulonglong2 q0 = qr[i],     k0 = kr[i];
                ulonglong2 q1 = qr[i + 1], k1 = kr[i + 1];
                ffma2(p0, q0.x, k0.x); ffma2(p1, q0.y, k0.y);
                ffma2(p0, q1.x, k1.x); ffma2(p1, q1.y, k1.y);
            }
            float a0, a1, a2, a3;
            unpack2(p0, a0, a1); unpack2(p1, a2, a3);
            float s = (a0 + a1 + a2 + a3) * 0.125f;
            sv[t] = s;
            mx = fmaxf(mx, s);
        }
#pragma unroll
        for (int o = 16; o; o >>= 1) mx = fmaxf(mx, __shfl_xor_sync(0xffffffffu, mx, o));
        float sum = 0.f;
        for (int t = 0; t < jcnt; t++) { float e = expf(sv[t] - mx); sv[t] = e; sum += e; }
#pragma unroll
        for (int o = 16; o; o >>= 1) sum += __shfl_xor_sync(0xffffffffu, sum, o);
        float inv = 1.f / sum;
        for (int t = 0; t < jcnt; t++) {
            int j = t * 32 + lane;
            float p = sv[t] * inv;
            *(float2*)&psd[warp * 2 * Nl + 2 * j] = make_float2(p, p);
        }
        __syncwarp();

        // AV: each lane owns d = 2*lane, 2*lane+1
        u64 av[4] = {0ull, 0ull, 0ull, 0ull};
        const float* pw = &psd[warp * 2 * Nl];
        for (int j = 0; j < Nl; j += 4) {
            ffma2(av[0], *(const u64*)&pw[2 * j],     *(const u64*)&Vs[(j)     * 68 + 2 * lane]);
            ffma2(av[1], *(const u64*)&pw[2 * j + 2], *(const u64*)&Vs[(j + 1) * 68 + 2 * lane]);
            ffma2(av[2], *(const u64*)&pw[2 * j + 4], *(const u64*)&Vs[(j + 2) * 68 + 2 * lane]);
            ffma2(av[3], *(const u64*)&pw[2 * j + 6], *(const u64*)&Vs[(j + 3) * 68 + 2 * lane]);
        }
        float l0, h0, l1, h1, l2, h2, l3, h3;
        unpack2(av[0], l0, h0); unpack2(av[1], l1, h1);
        unpack2(av[2], l2, h2); unpack2(av[3], l3, h3);
        float e0 = (l0 + l1) + (l2 + l3);
        float e1 = (h0 + h1) + (h2 + h3);
        *(float2*)&out[((size_t)b * Nl + r) * DIM + h * 64 + 2 * lane] = make_float2(e0, e1);
        __syncwarp();
    }
}

// ---------------------------------------------------------------------------
// Upsample + concat (float4)
// ---------------------------------------------------------------------------
__global__ void concat_k(const float* __restrict__ l0, const float* __restrict__ l1,
                         const float* __restrict__ l2, float* __restrict__ cat)
{
    int idx4 = blockIdx.x * blockDim.x + threadIdx.x;
    const int total4 = BB * NNODE * 3 * DIM / 4;
    if (idx4 >= total4) return;
    int c4 = idx4 % (3 * DIM / 4);
    int n  = (idx4 / (3 * DIM / 4)) % NNODE;
    int b  = idx4 / ((3 * DIM / 4) * NNODE);
    int col = c4 * 4, l = col >> 9, d = col & 511;
    const float* src = (l == 0) ? l0 : (l == 1) ? l1 : l2;
    int Nl = NNODE >> l;
    ((float4*)cat)[idx4] = *(const float4*)&src[((size_t)b * Nl + (n >> l)) * DIM + d];
}

// ---------------------------------------------------------------------------
// LayerNorm over last dim (512)
// ---------------------------------------------------------------------------
__global__ void ln_k(const float* __restrict__ in, const float* __restrict__ g,
                     const float* __restrict__ bta, float* __restrict__ out)
{
    const int row = blockIdx.x, t = threadIdx.x;
    const int warp = t >> 5, lane = t & 31;
    float4 v = ((const float4*)(in + (size_t)row * DIM))[t];
    __shared__ float red[4];

    float s = v.x + v.y + v.z + v.w;
#pragma unroll
    for (int o = 16; o; o >>= 1) s += __shfl_xor_sync(0xffffffffu, s, o);
    if (lane == 0) red[warp] = s;
    __syncthreads();
    float mean = (red[0] + red[1] + red[2] + red[3]) * (1.f / DIM);
    __syncthreads();

    float dx = v.x - mean, dy = v.y - mean, dz = v.z - mean, dw = v.w - mean;
    float s2 = dx * dx + dy * dy + dz * dz + dw * dw;
#pragma unroll
    for (int o = 16; o; o >>= 1) s2 += __shfl_xor_sync(0xffffffffu, s2, o);
    if (lane == 0) red[warp] = s2;
    __syncthreads();
    float var = (red[0] + red[1] + red[2] + red[3]) * (1.f / DIM);
    float inv = 1.f / sqrtf(var + 1e-5f);

    float4 gv = ((const float4*)g)[t];
    float4 bv = ((const float4*)bta)[t];
    float4 r;
    r.x = dx * inv * gv.x + bv.x;
    r.y = dy * inv * gv.y + bv.y;
    r.z = dz * inv * gv.z + bv.z;
    r.w = dw * inv * gv.w + bv.w;
    ((float4*)(out + (size_t)row * DIM))[t] = r;
}

// ---------------------------------------------------------------------------
// Repack We1[1024,512] -> wef[512,1024] (hi|hj column blocks) + fused bias
// ---------------------------------------------------------------------------
__global__ void repack_k(const float* __restrict__ We1, const float* __restrict__ be1,
                         float* __restrict__ wef, float* __restrict__ bef)
{
    int idx = blockIdx.x * blockDim.x + threadIdx.x;
    if (idx < DIM * 2 * DIM) {
        int k = idx >> 10, n = idx & 1023;
        wef[idx] = (n < DIM) ? We1[(size_t)k * DIM + n]
                             : We1[(size_t)(DIM + k) * DIM + (n - DIM)];
    }
    if (idx < 2 * DIM) bef[idx] = (idx < DIM) ? 0.f : be1[idx - DIM];
}

// ---------------------------------------------------------------------------
// Edge scores from merged ef buffer (row stride 1024: [hi | hj]).
// sc[b,i,j] = sum_d relu(hi[i,d] + hj[j,d]) * w2[d]; diag -> -1e30
// 64x32 tile, 256 threads (4i x 2j per thread), grid (8,4,B)
// ---------------------------------------------------------------------------
__global__ void scores_k(const float* __restrict__ ef, const float* __restrict__ w2,
                         float* __restrict__ sc)
{
    __shared__ float His[16][68];
    __shared__ float Hjs[16][36];
    __shared__ float W2s[16];
    const int b = blockIdx.z;
    const int i0 = blockIdx.y * 64, j0 = blockIdx.x * 32;
    const int tid = threadIdx.x;
    const int tx = tid & 15, ty = tid >> 4;
    const float* hib = ef + ((size_t)b * NNODE + i0) * (2 * DIM);
    const float* hjb = ef + ((size_t)b * NNODE + j0) * (2 * DIM) + DIM;

    float acc[4][2];
#pragma unroll
    for (int i = 0; i < 4; i++) { acc[i][0] = 0.f; acc[i][1] = 0.f; }

    const int ir = tid >> 2, ic = tid & 3;     // His load: 64 rows x 4 float4
    const int jr = tid >> 3, jc = tid & 7;     // Hjs load: 32 rows x 8 float2

    for (int k0 = 0; k0 < DIM; k0 += 16) {
        float4 a = *(const float4*)&hib[(size_t)ir * (2 * DIM) + k0 + ic * 4];
        His[ic * 4 + 0][ir] = a.x; His[ic * 4 + 1][ir] = a.y;
        His[ic * 4 + 2][ir] = a.z; His[ic * 4 + 3][ir] = a.w;
        float2 c = *(const float2*)&hjb[(size_t)jr * (2 * DIM) + k0 + jc * 2];
        Hjs[jc * 2 + 0][jr] = c.x; Hjs[jc * 2 + 1][jr] = c.y;
        if (tid < 16) W2s[tid] = w2[k0 + tid];
        __syncthreads();
#pragma unroll
        for (int kk = 0; kk < 16; kk++) {
            float4 h4 = *(const float4*)&His[kk][ty * 4];
            float2 j2 = *(const float2*)&Hjs[kk][tx * 2];
            float w = W2s[kk];
            float hv[4] = {h4.x, h4.y, h4.z, h4.w};
#pragma unroll
            for (int i = 0; i < 4; i++) {
                acc[i][0] += fmaxf(hv[i] + j2.x, 0.f) * w;
                acc[i][1] += fmaxf(hv[i] + j2.y, 0.f) * w;
            }
        }
        __syncthreads();
    }

#pragma unroll
    for (int i = 0; i < 4; i++) {
        int gi = i0 + ty * 4 + i;
#pragma unroll
        for (int j = 0; j < 2; j++) {
            int gj = j0 + tx * 2 + j;
            sc[((size_t)b * NNODE + gi) * NNODE + gj] = (gi == gj) ? -1e30f : acc[i][j];
        }
    }
}

// ---------------------------------------------------------------------------
// Top-k (k=25) per row, warp per row; zeroes its row first.
// ---------------------------------------------------------------------------
__global__ void topk_k(const float* __restrict__ sc, float* __restrict__ adj)
{
    const int warp = threadIdx.x >> 5, lane = threadIdx.x & 31;
    const int row = blockIdx.x * 8 + warp;
    const float* s = sc + (size_t)row * NNODE;
    float v[8];
#pragma unroll
    for (int t = 0; t < 8; t++) v[t] = s[t * 32 + lane];
    float* arow = adj + (size_t)row * NNODE;
#pragma unroll
    for (int t = 0; t < 8; t++) arow[t * 32 + lane] = 0.f;
    __syncwarp();

    for (int it = 0; it < KSP; it++) {
        float bv = -3e38f; int bi = 0;
#pragma unroll
        for (int t = 0; t < 8; t++) {
            int j = t * 32 + lane;
            if (v[t] > bv) { bv = v[t]; bi = j; }
        }
#pragma unroll
        for (int o = 16; o; o >>= 1) {
            float ov = __shfl_xor_sync(0xffffffffu, bv, o);
            int   oi = __shfl_xor_sync(0xffffffffu, bi, o);
            if (ov > bv || (ov == bv && oi < bi)) { bv = ov; bi = oi; }
        }
        if (lane == (bi & 31)) v[bi >> 5] = -3e38f;
        if (lane == 0) arow[bi] = 1.0f;
        __syncwarp();
    }
}

// ---------------------------------------------------------------------------
// Host orchestration
// ---------------------------------------------------------------------------
static float* symaddr(const void* s)
{
    void* p = nullptr;
    cudaGetSymbolAddress(&p, s);
    return (float*)p;
}

extern "C" void kernel_launch(void* const* d_in, const int* in_sizes, int n_in,
                              void* d_out, int out_size)
{
    const float* x      = (const float*)d_in[0];
    const float* Wqkv   = (const float*)d_in[2];
    const float* bqkv   = (const float*)d_in[3];
    const float* Wo     = (const float*)d_in[4];
    const float* bo     = (const float*)d_in[5];
    const float* Wp1    = (const float*)d_in[6];
    const float* bp1    = (const float*)d_in[7];
    const float* Wp2    = (const float*)d_in[8];
    const float* bp2    = (const float*)d_in[9];
    const float* Wfuse  = (const float*)d_in[10];
    const float* bfuse  = (const float*)d_in[11];
    const float* ln_g   = (const float*)d_in[12];
    const float* ln_b   = (const float*)d_in[13];
    const float* We1    = (const float*)d_in[14];
    const float* be1    = (const float*)d_in[15];
    const float* We2    = (const float*)d_in[16];
    const float* Ws_qkv = (const float*)d_in[18];
    const float* bs_qkv = (const float*)d_in[19];
    const float* Ws_o   = (const float*)d_in[20];
    const float* bs_o   = (const float*)d_in[21];

    float* out_att = (float*)d_out;                      // [B,N,D]
    float* out_adj = out_att + (size_t)BB * NNODE * DIM; // [B,N,N]

    float* cur  = symaddr(g_cur);
    float* qkv  = symaddr(g_qkv);
    float* atto = symaddr(g_atto);
    float* lvl0 = symaddr(g_lvl0);
    float* lvl1 = symaddr(g_lvl1);
    float* lvl2 = symaddr(g_lvl2);
    float* t1   = symaddr(g_t1);
    float* pbuf = symaddr(g_p);
    float* cat  = symaddr(g_cat);
    float* hier = symaddr(g_hier);
    float* ef   = symaddr(g_ef);
    float* wef  = symaddr(g_wef);
    float* bef  = symaddr(g_bef);
    float* sc   = symaddr(g_sc);

    cudaFuncSetAttribute(attn_k, cudaFuncAttributeMaxDynamicSharedMemorySize, 160000);

    float* lvls[3] = {lvl0, lvl1, lvl2};
    const float* curp = x;

    // repack We1 early (independent of everything else)
    repack_k<<<(DIM * 2 * DIM + 255) / 256, 256>>>(We1, be1, wef, bef);

    for (int l = 0; l < 3; l++) {
        const int Nl = NNODE >> l;
        const int M  = BB * Nl;
        sgemm_k<<<dim3(3 * DIM / 64, M / 64), 128>>>(
            curp, Wqkv + (size_t)l * DIM * 3 * DIM, bqkv + (size_t)l * 3 * DIM,
            qkv, M, DIM, 3 * DIM, 0);
        size_t smem = (size_t)(Nl * 68 * 2 + 8 * 64 + 8 * 2 * Nl) * sizeof(float);
        attn_k<<<dim3(BB * NH, 4), 256, smem>>>(qkv, atto, Nl);
        sgemm_k<<<dim3(DIM / 64, M / 64), 128>>>(
            atto, Wo + (size_t)l * DIM * DIM, bo + (size_t)l * DIM,
            lvls[l], M, DIM, DIM, 0);
        if (l < 2) {
            sgemm_k<<<dim3(DIM / 2 / 64, M / 64), 128>>>(
                lvls[l], Wp1 + (size_t)l * DIM * (DIM / 2), bp1 + (size_t)l * (DIM / 2),
                t1, M, DIM, DIM / 2, 1);
            // Wp2 with fused pairwise pooling -> cur (M/2 rows)
            sgemm_k<<<dim3(DIM / 64, M / 64), 128>>>(
                t1, Wp2 + (size_t)l * (DIM / 2) * DIM, bp2 + (size_t)l * DIM,
                cur, M, DIM / 2, DIM, 2);
            curp = cur;
        }
    }

    // fuse: concat upsampled levels -> GEMM(relu) -> LayerNorm
    {
        const int total4 = BB * NNODE * 3 * DIM / 4;
        concat_k<<<(total4 + 255) / 256, 256>>>(lvl0, lvl1, lvl2, cat);
        sgemm_k<<<dim3(DIM / 64, BB * NNODE / 64), 128>>>(
            cat, Wfuse, bfuse, pbuf, BB * NNODE, 3 * DIM, DIM, 1);
        ln_k<<<BB * NNODE, 128>>>(pbuf, ln_g, ln_b, hier);
    }

    // sparse edge scoring + top-k (merged hi|hj GEMM)
    {
        sgemm_k<<<dim3(2 * DIM / 64, BB * NNODE / 64), 128>>>(
            hier, wef, bef, ef, BB * NNODE, DIM, 2 * DIM, 0);
        scores_k<<<dim3(NNODE / 32, NNODE / 64, BB), 256>>>(ef, We2, sc);
        topk_k<<<BB * NNODE / 8, 256>>>(sc, out_adj);
    }

    // final MHA on hier -> attended output
    {
        const int M = BB * NNODE;
        sgemm_k<<<dim3(3 * DIM / 64, M / 64), 128>>>(
            hier, Ws_qkv, bs_qkv, qkv, M, DIM, 3 * DIM, 0);
        size_t smem = (size_t)(NNODE * 68 * 2 + 8 * 64 + 8 * 2 * NNODE) * sizeof(float);
        attn_k<<<dim3(BB * NH, 4), 256, smem>>>(qkv, atto, NNODE);
        sgemm_k<<<dim3(DIM / 64, M / 64), 128>>>(
            atto, Ws_o, bs_o, out_att, M, DIM, DIM, 0);
    }
}

// round 7
// speedup vs baseline: 1.6578x; 1.2956x over previous
#include <cuda_runtime.h>
#include <math.h>

#define BB 4
#define NNODE 256
#define DIM 512
#define NH 8
#define KSP 25

// ---------------------------------------------------------------------------
// Scratch (no allocations allowed anywhere)
// ---------------------------------------------------------------------------
__device__ float g_cur [BB*NNODE*DIM];
__device__ float g_qkv [BB*NNODE*3*DIM];
__device__ float g_atto[BB*NNODE*DIM];
__device__ float g_lvl0[BB*NNODE*DIM];
__device__ float g_lvl1[BB*(NNODE/2)*DIM];
__device__ float g_lvl2[BB*(NNODE/4)*DIM];
__device__ float g_t1  [BB*NNODE*(DIM/2)];
__device__ float g_p   [BB*NNODE*DIM];
__device__ float g_cat [BB*NNODE*3*DIM];
__device__ float g_hier[BB*NNODE*DIM];
__device__ float g_ef  [BB*NNODE*2*DIM];
__device__ float g_wef [DIM*2*DIM];
__device__ float g_bef [2*DIM];
__device__ float g_sc  [BB*NNODE*NNODE];

typedef unsigned long long u64;

__device__ __forceinline__ void ffma2(u64& d, u64 a, u64 b) {
    asm("fma.rn.f32x2 %0, %1, %2, %0;" : "+l"(d) : "l"(a), "l"(b));
}
__device__ __forceinline__ void unpack2(u64 v, float& lo, float& hi) {
    asm("mov.b64 {%0, %1}, %2;" : "=f"(lo), "=f"(hi) : "l"(v));
}

// ---------------------------------------------------------------------------
// SGEMM: C[M,Nc] = A[M,K] @ W[K,Nc] (+bias) (+relu / pool)
// 256 threads (8 warps), 64x64 tile, 4Mx4N per thread, BK=16, double-buffered.
// f32x2 accumulators pair adjacent N columns. B tile is a plain layout (pairs
// load directly); A tile is stored duplicated (a,a) — A reads are warp-
// broadcast so the duplication is cheap. Zero packing MOVs in the inner loop.
// mode: 0 = bias, 1 = bias+relu, 2 = pairwise-pool rows (0.5*(r0+r1)+bias)
// ---------------------------------------------------------------------------
__global__ void __launch_bounds__(256)
sgemm_k(const float* __restrict__ A, const float* __restrict__ W,
        const float* __restrict__ bias, float* __restrict__ C,
        int M, int K, int Nc, int mode)
{
    __shared__ float Ad[2][16][136];   // duplicated A: Ad[k][2r]=Ad[k][2r+1]=A[r]
    __shared__ float Bs[2][16][64];    // plain B tile

    const int bm = blockIdx.y * 64, bn = blockIdx.x * 64;
    const int tid = threadIdx.x;
    const int ty = tid >> 4;        // 0..15 : rows ty*4 .. ty*4+3
    const int tx = tid & 15;        // 0..15 : cols tx*4 .. tx*4+3 (2 n-pairs)

    u64 acc[4][2];                  // [m][n-pair]
#pragma unroll
    for (int i = 0; i < 4; i++) { acc[i][0] = 0ull; acc[i][1] = 0ull; }

    const int nk = K >> 4;
    const int ar = tid >> 2, ac = tid & 3;     // A: row ar, float4 k-col ac
    const int bk = tid >> 4, bn4 = tid & 15;   // B: k row bk, float4 col bn4

    float4 areg, breg;

    areg = *(const float4*)&A[(size_t)(bm + ar) * K + ac * 4];
    breg = *(const float4*)&W[(size_t)bk * Nc + bn + bn4 * 4];

    {
        *(float2*)&Ad[0][ac * 4 + 0][2 * ar] = make_float2(areg.x, areg.x);
        *(float2*)&Ad[0][ac * 4 + 1][2 * ar] = make_float2(areg.y, areg.y);
        *(float2*)&Ad[0][ac * 4 + 2][2 * ar] = make_float2(areg.z, areg.z);
        *(float2*)&Ad[0][ac * 4 + 3][2 * ar] = make_float2(areg.w, areg.w);
        *(float4*)&Bs[0][bk][bn4 * 4] = breg;
    }
    __syncthreads();

    for (int k0 = 0; k0 < nk; k0++) {
        const int buf = k0 & 1;
        if (k0 + 1 < nk) {
            const int kb = (k0 + 1) << 4;
            areg = *(const float4*)&A[(size_t)(bm + ar) * K + kb + ac * 4];
            breg = *(const float4*)&W[(size_t)(kb + bk) * Nc + bn + bn4 * 4];
        }
#pragma unroll
        for (int kk = 0; kk < 16; kk++) {
            ulonglong2 a01 = *(const ulonglong2*)&Ad[buf][kk][ty * 8];      // rows ty*4, +1 (dup)
            ulonglong2 a23 = *(const ulonglong2*)&Ad[buf][kk][ty * 8 + 4];  // rows +2, +3 (dup)
            ulonglong2 b   = *(const ulonglong2*)&Bs[buf][kk][tx * 4];      // pairs (n0,n1),(n2,n3)
            ffma2(acc[0][0], a01.x, b.x); ffma2(acc[0][1], a01.x, b.y);
            ffma2(acc[1][0], a01.y, b.x); ffma2(acc[1][1], a01.y, b.y);
            ffma2(acc[2][0], a23.x, b.x); ffma2(acc[2][1], a23.x, b.y);
            ffma2(acc[3][0], a23.y, b.x); ffma2(acc[3][1], a23.y, b.y);
        }
        if (k0 + 1 < nk) {
            const int nb = buf ^ 1;
            *(float2*)&Ad[nb][ac * 4 + 0][2 * ar] = make_float2(areg.x, areg.x);
            *(float2*)&Ad[nb][ac * 4 + 1][2 * ar] = make_float2(areg.y, areg.y);
            *(float2*)&Ad[nb][ac * 4 + 2][2 * ar] = make_float2(areg.z, areg.z);
            *(float2*)&Ad[nb][ac * 4 + 3][2 * ar] = make_float2(areg.w, areg.w);
            *(float4*)&Bs[nb][bk][bn4 * 4] = breg;
        }
        __syncthreads();
    }

    float4 bb = make_float4(0.f, 0.f, 0.f, 0.f);
    if (bias) bb = *(const float4*)&bias[bn + tx * 4];
    const float bv[4] = {bb.x, bb.y, bb.z, bb.w};

    float c[4][4];
#pragma unroll
    for (int m = 0; m < 4; m++) {
        unpack2(acc[m][0], c[m][0], c[m][1]);
        unpack2(acc[m][1], c[m][2], c[m][3]);
    }

    if (mode == 2) {
        // rows (ty*4, ty*4+1) -> pooled row bm/2 + ty*2; (+2,+3) -> +1
#pragma unroll
        for (int p = 0; p < 2; p++) {
            float v[4];
#pragma unroll
            for (int n = 0; n < 4; n++)
                v[n] = 0.5f * (c[2 * p][n] + c[2 * p + 1][n]) + bv[n];
            int pr = (bm >> 1) + ty * 2 + p;
            *(float4*)&C[(size_t)pr * Nc + bn + tx * 4] = make_float4(v[0], v[1], v[2], v[3]);
        }
    } else {
#pragma unroll
        for (int m = 0; m < 4; m++) {
            float v[4];
#pragma unroll
            for (int n = 0; n < 4; n++) {
                v[n] = c[m][n] + bv[n];
                if (mode == 1) v[n] = fmaxf(v[n], 0.f);
            }
            int row = bm + ty * 4 + m;
            *(float4*)&C[(size_t)row * Nc + bn + tx * 4] = make_float4(v[0], v[1], v[2], v[3]);
        }
    }
}

// ---------------------------------------------------------------------------
// Multi-head attention: qkv [B, Nl, 3*DIM] -> out [B, Nl, DIM]
// grid (B*NH, 4), block 256. K/V in shared (pitch 68), f32x2 QK dot,
// duplicated-probability AV phase.
// ---------------------------------------------------------------------------
__global__ void attn_k(const float* __restrict__ qkv, float* __restrict__ out, int Nl)
{
    extern __shared__ float sm[];
    float* Ks  = sm;                    // Nl*68
    float* Vs  = Ks + Nl * 68;          // Nl*68
    float* qs  = Vs + Nl * 68;          // 8*64
    float* psd = qs + 8 * 64;           // 8 * 2*Nl (duplicated probs)

    const int b = blockIdx.x >> 3, h = blockIdx.x & 7;
    const float* base = qkv + (size_t)b * Nl * (3 * DIM);
    const int tid = threadIdx.x, warp = tid >> 5, lane = tid & 31;

    for (int idx = tid; idx < Nl * 16; idx += 256) {
        int n = idx >> 4, dv = idx & 15;
        const float* rowp = base + (size_t)n * (3 * DIM) + h * 64 + dv * 4;
        *(float4*)&Ks[n * 68 + dv * 4] = *(const float4*)(rowp + DIM);
        *(float4*)&Vs[n * 68 + dv * 4] = *(const float4*)(rowp + 2 * DIM);
    }
    __syncthreads();

    const int jcnt = Nl >> 5;
    for (int r = blockIdx.y * 8 + warp; r < Nl; r += 8 * gridDim.y) {
        if (lane < 16)
            ((float4*)&qs[warp * 64])[lane] =
                *(const float4*)&base[(size_t)r * (3 * DIM) + h * 64 + lane * 4];
        __syncwarp();

        const ulonglong2* qr = (const ulonglong2*)&qs[warp * 64];
        float sv[8];
        float mx = -1e30f;
        for (int t = 0; t < jcnt; t++) {
            int j = t * 32 + lane;
            const ulonglong2* kr = (const ulonglong2*)&Ks[j * 68];
            u64 p0 = 0ull, p1 = 0ull;
#pragma unroll
            for (int i = 0; i < 16; i += 2) {
                ulonglong2 q0 = qr[i],     k0 = kr[i];
                ulonglong2 q1 = qr[i + 1], k1 = kr[i + 1];
                ffma2(p0, q0.x, k0.x); ffma2(p1, q0.y, k0.y);
                ffma2(p0, q1.x, k1.x); ffma2(p1, q1.y, k1.y);
            }
            float a0, a1, a2, a3;
            unpack2(p0, a0, a1); unpack2(p1, a2, a3);
            float s = (a0 + a1 + a2 + a3) * 0.125f;
            sv[t] = s;
            mx = fmaxf(mx, s);
        }
#pragma unroll
        for (int o = 16; o; o >>= 1) mx = fmaxf(mx, __shfl_xor_sync(0xffffffffu, mx, o));
        float sum = 0.f;
        for (int t = 0; t < jcnt; t++) { float e = expf(sv[t] - mx); sv[t] = e; sum += e; }
#pragma unroll
        for (int o = 16; o; o >>= 1) sum += __shfl_xor_sync(0xffffffffu, sum, o);
        float inv = 1.f / sum;
        for (int t = 0; t < jcnt; t++) {
            int j = t * 32 + lane;
            float p = sv[t] * inv;
            *(float2*)&psd[warp * 2 * Nl + 2 * j] = make_float2(p, p);
        }
        __syncwarp();

        // AV: each lane owns d = 2*lane, 2*lane+1
        u64 av[4] = {0ull, 0ull, 0ull, 0ull};
        const float* pw = &psd[warp * 2 * Nl];
        for (int j = 0; j < Nl; j += 4) {
            ffma2(av[0], *(const u64*)&pw[2 * j],     *(const u64*)&Vs[(j)     * 68 + 2 * lane]);
            ffma2(av[1], *(const u64*)&pw[2 * j + 2], *(const u64*)&Vs[(j + 1) * 68 + 2 * lane]);
            ffma2(av[2], *(const u64*)&pw[2 * j + 4], *(const u64*)&Vs[(j + 2) * 68 + 2 * lane]);
            ffma2(av[3], *(const u64*)&pw[2 * j + 6], *(const u64*)&Vs[(j + 3) * 68 + 2 * lane]);
        }
        float l0, h0, l1, h1, l2, h2, l3, h3;
        unpack2(av[0], l0, h0); unpack2(av[1], l1, h1);
        unpack2(av[2], l2, h2); unpack2(av[3], l3, h3);
        float e0 = (l0 + l1) + (l2 + l3);
        float e1 = (h0 + h1) + (h2 + h3);
        *(float2*)&out[((size_t)b * Nl + r) * DIM + h * 64 + 2 * lane] = make_float2(e0, e1);
        __syncwarp();
    }
}

// ---------------------------------------------------------------------------
// Upsample + concat (float4)
// ---------------------------------------------------------------------------
__global__ void concat_k(const float* __restrict__ l0, const float* __restrict__ l1,
                         const float* __restrict__ l2, float* __restrict__ cat)
{
    int idx4 = blockIdx.x * blockDim.x + threadIdx.x;
    const int total4 = BB * NNODE * 3 * DIM / 4;
    if (idx4 >= total4) return;
    int c4 = idx4 % (3 * DIM / 4);
    int n  = (idx4 / (3 * DIM / 4)) % NNODE;
    int b  = idx4 / ((3 * DIM / 4) * NNODE);
    int col = c4 * 4, l = col >> 9, d = col & 511;
    const float* src = (l == 0) ? l0 : (l == 1) ? l1 : l2;
    int Nl = NNODE >> l;
    ((float4*)cat)[idx4] = *(const float4*)&src[((size_t)b * Nl + (n >> l)) * DIM + d];
}

// ---------------------------------------------------------------------------
// LayerNorm over last dim (512)
// ---------------------------------------------------------------------------
__global__ void ln_k(const float* __restrict__ in, const float* __restrict__ g,
                     const float* __restrict__ bta, float* __restrict__ out)
{
    const int row = blockIdx.x, t = threadIdx.x;
    const int warp = t >> 5, lane = t & 31;
    float4 v = ((const float4*)(in + (size_t)row * DIM))[t];
    __shared__ float red[4];

    float s = v.x + v.y + v.z + v.w;
#pragma unroll
    for (int o = 16; o; o >>= 1) s += __shfl_xor_sync(0xffffffffu, s, o);
    if (lane == 0) red[warp] = s;
    __syncthreads();
    float mean = (red[0] + red[1] + red[2] + red[3]) * (1.f / DIM);
    __syncthreads();

    float dx = v.x - mean, dy = v.y - mean, dz = v.z - mean, dw = v.w - mean;
    float s2 = dx * dx + dy * dy + dz * dz + dw * dw;
#pragma unroll
    for (int o = 16; o; o >>= 1) s2 += __shfl_xor_sync(0xffffffffu, s2, o);
    if (lane == 0) red[warp] = s2;
    __syncthreads();
    float var = (red[0] + red[1] + red[2] + red[3]) * (1.f / DIM);
    float inv = 1.f / sqrtf(var + 1e-5f);

    float4 gv = ((const float4*)g)[t];
    float4 bv = ((const float4*)bta)[t];
    float4 r;
    r.x = dx * inv * gv.x + bv.x;
    r.y = dy * inv * gv.y + bv.y;
    r.z = dz * inv * gv.z + bv.z;
    r.w = dw * inv * gv.w + bv.w;
    ((float4*)(out + (size_t)row * DIM))[t] = r;
}

// ---------------------------------------------------------------------------
// Repack We1[1024,512] -> wef[512,1024] (hi|hj column blocks) + fused bias
// ---------------------------------------------------------------------------
__global__ void repack_k(const float* __restrict__ We1, const float* __restrict__ be1,
                         float* __restrict__ wef, float* __restrict__ bef)
{
    int idx = blockIdx.x * blockDim.x + threadIdx.x;
    if (idx < DIM * 2 * DIM) {
        int k = idx >> 10, n = idx & 1023;
        wef[idx] = (n < DIM) ? We1[(size_t)k * DIM + n]
                             : We1[(size_t)(DIM + k) * DIM + (n - DIM)];
    }
    if (idx < 2 * DIM) bef[idx] = (idx < DIM) ? 0.f : be1[idx - DIM];
}

// ---------------------------------------------------------------------------
// Edge scores from merged ef buffer (row stride 1024: [hi | hj]).
// sc[b,i,j] = sum_d relu(hi[i,d] + hj[j,d]) * w2[d]; diag -> -1e30
// 64x32 tile, 256 threads (4i x 2j per thread), grid (8,4,B)
// ---------------------------------------------------------------------------
__global__ void scores_k(const float* __restrict__ ef, const float* __restrict__ w2,
                         float* __restrict__ sc)
{
    __shared__ float His[16][68];
    __shared__ float Hjs[16][36];
    __shared__ float W2s[16];
    const int b = blockIdx.z;
    const int i0 = blockIdx.y * 64, j0 = blockIdx.x * 32;
    const int tid = threadIdx.x;
    const int tx = tid & 15, ty = tid >> 4;
    const float* hib = ef + ((size_t)b * NNODE + i0) * (2 * DIM);
    const float* hjb = ef + ((size_t)b * NNODE + j0) * (2 * DIM) + DIM;

    float acc[4][2];
#pragma unroll
    for (int i = 0; i < 4; i++) { acc[i][0] = 0.f; acc[i][1] = 0.f; }

    const int ir = tid >> 2, ic = tid & 3;     // His load: 64 rows x 4 float4
    const int jr = tid >> 3, jc = tid & 7;     // Hjs load: 32 rows x 8 float2

    for (int k0 = 0; k0 < DIM; k0 += 16) {
        float4 a = *(const float4*)&hib[(size_t)ir * (2 * DIM) + k0 + ic * 4];
        His[ic * 4 + 0][ir] = a.x; His[ic * 4 + 1][ir] = a.y;
        His[ic * 4 + 2][ir] = a.z; His[ic * 4 + 3][ir] = a.w;
        float2 c = *(const float2*)&hjb[(size_t)jr * (2 * DIM) + k0 + jc * 2];
        Hjs[jc * 2 + 0][jr] = c.x; Hjs[jc * 2 + 1][jr] = c.y;
        if (tid < 16) W2s[tid] = w2[k0 + tid];
        __syncthreads();
#pragma unroll
        for (int kk = 0; kk < 16; kk++) {
            float4 h4 = *(const float4*)&His[kk][ty * 4];
            float2 j2 = *(const float2*)&Hjs[kk][tx * 2];
            float w = W2s[kk];
            float hv[4] = {h4.x, h4.y, h4.z, h4.w};
#pragma unroll
            for (int i = 0; i < 4; i++) {
                acc[i][0] += fmaxf(hv[i] + j2.x, 0.f) * w;
                acc[i][1] += fmaxf(hv[i] + j2.y, 0.f) * w;
            }
        }
        __syncthreads();
    }

#pragma unroll
    for (int i = 0; i < 4; i++) {
        int gi = i0 + ty * 4 + i;
#pragma unroll
        for (int j = 0; j < 2; j++) {
            int gj = j0 + tx * 2 + j;
            sc[((size_t)b * NNODE + gi) * NNODE + gj] = (gi == gj) ? -1e30f : acc[i][j];
        }
    }
}

// ---------------------------------------------------------------------------
// Top-k (k=25) per row, warp per row; zeroes its row first.
// ---------------------------------------------------------------------------
__global__ void topk_k(const float* __restrict__ sc, float* __restrict__ adj)
{
    const int warp = threadIdx.x >> 5, lane = threadIdx.x & 31;
    const int row = blockIdx.x * 8 + warp;
    const float* s = sc + (size_t)row * NNODE;
    float v[8];
#pragma unroll
    for (int t = 0; t < 8; t++) v[t] = s[t * 32 + lane];
    float* arow = adj + (size_t)row * NNODE;
#pragma unroll
    for (int t = 0; t < 8; t++) arow[t * 32 + lane] = 0.f;
    __syncwarp();

    for (int it = 0; it < KSP; it++) {
        float bv = -3e38f; int bi = 0;
#pragma unroll
        for (int t = 0; t < 8; t++) {
            int j = t * 32 + lane;
            if (v[t] > bv) { bv = v[t]; bi = j; }
        }
#pragma unroll
        for (int o = 16; o; o >>= 1) {
            float ov = __shfl_xor_sync(0xffffffffu, bv, o);
            int   oi = __shfl_xor_sync(0xffffffffu, bi, o);
            if (ov > bv || (ov == bv && oi < bi)) { bv = ov; bi = oi; }
        }
        if (lane == (bi & 31)) v[bi >> 5] = -3e38f;
        if (lane == 0) arow[bi] = 1.0f;
        __syncwarp();
    }
}

// ---------------------------------------------------------------------------
// Host orchestration
// ---------------------------------------------------------------------------
static float* symaddr(const void* s)
{
    void* p = nullptr;
    cudaGetSymbolAddress(&p, s);
    return (float*)p;
}

extern "C" void kernel_launch(void* const* d_in, const int* in_sizes, int n_in,
                              void* d_out, int out_size)
{
    const float* x      = (const float*)d_in[0];
    const float* Wqkv   = (const float*)d_in[2];
    const float* bqkv   = (const float*)d_in[3];
    const float* Wo     = (const float*)d_in[4];
    const float* bo     = (const float*)d_in[5];
    const float* Wp1    = (const float*)d_in[6];
    const float* bp1    = (const float*)d_in[7];
    const float* Wp2    = (const float*)d_in[8];
    const float* bp2    = (const float*)d_in[9];
    const float* Wfuse  = (const float*)d_in[10];
    const float* bfuse  = (const float*)d_in[11];
    const float* ln_g   = (const float*)d_in[12];
    const float* ln_b   = (const float*)d_in[13];
    const float* We1    = (const float*)d_in[14];
    const float* be1    = (const float*)d_in[15];
    const float* We2    = (const float*)d_in[16];
    const float* Ws_qkv = (const float*)d_in[18];
    const float* bs_qkv = (const float*)d_in[19];
    const float* Ws_o   = (const float*)d_in[20];
    const float* bs_o   = (const float*)d_in[21];

    float* out_att = (float*)d_out;                      // [B,N,D]
    float* out_adj = out_att + (size_t)BB * NNODE * DIM; // [B,N,N]

    float* cur  = symaddr(g_cur);
    float* qkv  = symaddr(g_qkv);
    float* atto = symaddr(g_atto);
    float* lvl0 = symaddr(g_lvl0);
    float* lvl1 = symaddr(g_lvl1);
    float* lvl2 = symaddr(g_lvl2);
    float* t1   = symaddr(g_t1);
    float* pbuf = symaddr(g_p);
    float* cat  = symaddr(g_cat);
    float* hier = symaddr(g_hier);
    float* ef   = symaddr(g_ef);
    float* wef  = symaddr(g_wef);
    float* bef  = symaddr(g_bef);
    float* sc   = symaddr(g_sc);

    cudaFuncSetAttribute(attn_k, cudaFuncAttributeMaxDynamicSharedMemorySize, 160000);

    float* lvls[3] = {lvl0, lvl1, lvl2};
    const float* curp = x;

    // repack We1 early (independent of everything else)
    repack_k<<<(DIM * 2 * DIM + 255) / 256, 256>>>(We1, be1, wef, bef);

    for (int l = 0; l < 3; l++) {
        const int Nl = NNODE >> l;
        const int M  = BB * Nl;
        sgemm_k<<<dim3(3 * DIM / 64, M / 64), 256>>>(
            curp, Wqkv + (size_t)l * DIM * 3 * DIM, bqkv + (size_t)l * 3 * DIM,
            qkv, M, DIM, 3 * DIM, 0);
        size_t smem = (size_t)(Nl * 68 * 2 + 8 * 64 + 8 * 2 * Nl) * sizeof(float);
        attn_k<<<dim3(BB * NH, 4), 256, smem>>>(qkv, atto, Nl);
        sgemm_k<<<dim3(DIM / 64, M / 64), 256>>>(
            atto, Wo + (size_t)l * DIM * DIM, bo + (size_t)l * DIM,
            lvls[l], M, DIM, DIM, 0);
        if (l < 2) {
            sgemm_k<<<dim3(DIM / 2 / 64, M / 64), 256>>>(
                lvls[l], Wp1 + (size_t)l * DIM * (DIM / 2), bp1 + (size_t)l * (DIM / 2),
                t1, M, DIM, DIM / 2, 1);
            // Wp2 with fused pairwise pooling -> cur (M/2 rows)
            sgemm_k<<<dim3(DIM / 64, M / 64), 256>>>(
                t1, Wp2 + (size_t)l * (DIM / 2) * DIM, bp2 + (size_t)l * DIM,
                cur, M, DIM / 2, DIM, 2);
            curp = cur;
        }
    }

    // fuse: concat upsampled levels -> GEMM(relu) -> LayerNorm
    {
        const int total4 = BB * NNODE * 3 * DIM / 4;
        concat_k<<<(total4 + 255) / 256, 256>>>(lvl0, lvl1, lvl2, cat);
        sgemm_k<<<dim3(DIM / 64, BB * NNODE / 64), 256>>>(
            cat, Wfuse, bfuse, pbuf, BB * NNODE, 3 * DIM, DIM, 1);
        ln_k<<<BB * NNODE, 128>>>(pbuf, ln_g, ln_b, hier);
    }

    // sparse edge scoring + top-k (merged hi|hj GEMM)
    {
        sgemm_k<<<dim3(2 * DIM / 64, BB * NNODE / 64), 256>>>(
            hier, wef, bef, ef, BB * NNODE, DIM, 2 * DIM, 0);
        scores_k<<<dim3(NNODE / 32, NNODE / 64, BB), 256>>>(ef, We2, sc);
        topk_k<<<BB * NNODE / 8, 256>>>(sc, out_adj);
    }

    // final MHA on hier -> attended output
    {
        const int M = BB * NNODE;
        sgemm_k<<<dim3(3 * DIM / 64, M / 64), 256>>>(
            hier, Ws_qkv, bs_qkv, qkv, M, DIM, 3 * DIM, 0);
        size_t smem = (size_t)(NNODE * 68 * 2 + 8 * 64 + 8 * 2 * NNODE) * sizeof(float);
        attn_k<<<dim3(BB * NH, 4), 256, smem>>>(qkv, atto, NNODE);
        sgemm_k<<<dim3(DIM / 64, M / 64), 256>>>(
            atto, Ws_o, bs_o, out_att, M, DIM, DIM, 0);
    }
}

// round 8
// speedup vs baseline: 1.8400x; 1.1099x over previous
#include <cuda_runtime.h>
#include <math.h>

#define BB 4
#define NNODE 256
#define DIM 512
#define NH 8
#define KSP 25

// ---------------------------------------------------------------------------
// Scratch (no allocations allowed anywhere)
// ---------------------------------------------------------------------------
__device__ float g_cur [BB*NNODE*DIM];
__device__ float g_qkv [BB*NNODE*3*DIM];
__device__ float g_atto[BB*NNODE*DIM];
__device__ float g_lvl0[BB*NNODE*DIM];
__device__ float g_lvl1[BB*(NNODE/2)*DIM];
__device__ float g_lvl2[BB*(NNODE/4)*DIM];
__device__ float g_t1  [BB*NNODE*(DIM/2)];
__device__ float g_p   [BB*NNODE*DIM];
__device__ float g_cat [BB*NNODE*3*DIM];
__device__ float g_hier[BB*NNODE*DIM];
__device__ float g_ef  [BB*NNODE*2*DIM];
__device__ float g_wef [DIM*2*DIM];
__device__ float g_bef [2*DIM];
__device__ float g_sc  [BB*NNODE*NNODE];
__device__ float g_part[2*1024*1024];   // split-K partials (8 MB max)

typedef unsigned long long u64;

__device__ __forceinline__ void ffma2(u64& d, u64 a, u64 b) {
    asm("fma.rn.f32x2 %0, %1, %2, %0;" : "+l"(d) : "l"(a), "l"(b));
}
__device__ __forceinline__ void unpack2(u64 v, float& lo, float& hi) {
    asm("mov.b64 {%0, %1}, %2;" : "=f"(lo), "=f"(hi) : "l"(v));
}

// ---------------------------------------------------------------------------
// SGEMM: C[M,Nc] = A[M,K] @ W[K,Nc] (+bias) (+relu / pool)
// 256 threads (8 warps), 64x64 tile, 4Mx4N per thread, BK=16, double-buffered,
// f32x2 accumulators pairing adjacent N. Split-K via gridDim.z: each z-slice
// computes K/S and writes a raw partial plane; reduce_k finishes.
// mode: 0 = bias, 1 = bias+relu, 2 = pairwise-pool rows (0.5*(r0+r1)+bias)
// ---------------------------------------------------------------------------
__global__ void __launch_bounds__(256)
sgemm_k(const float* __restrict__ A, const float* __restrict__ W,
        const float* __restrict__ bias, float* __restrict__ C,
        int M, int K, int Nc, int mode, float* __restrict__ part)
{
    __shared__ float Ad[2][16][136];   // duplicated A: Ad[k][2r]=Ad[k][2r+1]=A[r]
    __shared__ float Bs[2][16][64];    // plain B tile

    const int S = gridDim.z, z = blockIdx.z;
    const int Ks = K / S;              // multiple of 16 by construction
    const int kbase = z * Ks;

    const int bm = blockIdx.y * 64, bn = blockIdx.x * 64;
    const int tid = threadIdx.x;
    const int ty = tid >> 4;        // 0..15 : rows ty*4 .. ty*4+3
    const int tx = tid & 15;        // 0..15 : cols tx*4 .. tx*4+3 (2 n-pairs)

    u64 acc[4][2];
#pragma unroll
    for (int i = 0; i < 4; i++) { acc[i][0] = 0ull; acc[i][1] = 0ull; }

    const int nk = Ks >> 4;
    const int ar = tid >> 2, ac = tid & 3;     // A: row ar, float4 k-col ac
    const int bk = tid >> 4, bn4 = tid & 15;   // B: k row bk, float4 col bn4

    float4 areg, breg;

    areg = *(const float4*)&A[(size_t)(bm + ar) * K + kbase + ac * 4];
    breg = *(const float4*)&W[(size_t)(kbase + bk) * Nc + bn + bn4 * 4];

    {
        *(float2*)&Ad[0][ac * 4 + 0][2 * ar] = make_float2(areg.x, areg.x);
        *(float2*)&Ad[0][ac * 4 + 1][2 * ar] = make_float2(areg.y, areg.y);
        *(float2*)&Ad[0][ac * 4 + 2][2 * ar] = make_float2(areg.z, areg.z);
        *(float2*)&Ad[0][ac * 4 + 3][2 * ar] = make_float2(areg.w, areg.w);
        *(float4*)&Bs[0][bk][bn4 * 4] = breg;
    }
    __syncthreads();

    for (int k0 = 0; k0 < nk; k0++) {
        const int buf = k0 & 1;
        if (k0 + 1 < nk) {
            const int kb = kbase + ((k0 + 1) << 4);
            areg = *(const float4*)&A[(size_t)(bm + ar) * K + kb + ac * 4];
            breg = *(const float4*)&W[(size_t)(kb + bk) * Nc + bn + bn4 * 4];
        }
#pragma unroll
        for (int kk = 0; kk < 16; kk++) {
            ulonglong2 a01 = *(const ulonglong2*)&Ad[buf][kk][ty * 8];
            ulonglong2 a23 = *(const ulonglong2*)&Ad[buf][kk][ty * 8 + 4];
            ulonglong2 b   = *(const ulonglong2*)&Bs[buf][kk][tx * 4];
            ffma2(acc[0][0], a01.x, b.x); ffma2(acc[0][1], a01.x, b.y);
            ffma2(acc[1][0], a01.y, b.x); ffma2(acc[1][1], a01.y, b.y);
            ffma2(acc[2][0], a23.x, b.x); ffma2(acc[2][1], a23.x, b.y);
            ffma2(acc[3][0], a23.y, b.x); ffma2(acc[3][1], a23.y, b.y);
        }
        if (k0 + 1 < nk) {
            const int nb = buf ^ 1;
            *(float2*)&Ad[nb][ac * 4 + 0][2 * ar] = make_float2(areg.x, areg.x);
            *(float2*)&Ad[nb][ac * 4 + 1][2 * ar] = make_float2(areg.y, areg.y);
            *(float2*)&Ad[nb][ac * 4 + 2][2 * ar] = make_float2(areg.z, areg.z);
            *(float2*)&Ad[nb][ac * 4 + 3][2 * ar] = make_float2(areg.w, areg.w);
            *(float4*)&Bs[nb][bk][bn4 * 4] = breg;
        }
        __syncthreads();
    }

    float c[4][4];
#pragma unroll
    for (int m = 0; m < 4; m++) {
        unpack2(acc[m][0], c[m][0], c[m][1]);
        unpack2(acc[m][1], c[m][2], c[m][3]);
    }

    if (S > 1) {
        // raw partial plane, no epilogue
        const size_t plane = (size_t)M * Nc;
#pragma unroll
        for (int m = 0; m < 4; m++) {
            int row = bm + ty * 4 + m;
            *(float4*)&part[z * plane + (size_t)row * Nc + bn + tx * 4] =
                make_float4(c[m][0], c[m][1], c[m][2], c[m][3]);
        }
        return;
    }

    float4 bb = make_float4(0.f, 0.f, 0.f, 0.f);
    if (bias) bb = *(const float4*)&bias[bn + tx * 4];
    const float bv[4] = {bb.x, bb.y, bb.z, bb.w};

    if (mode == 2) {
#pragma unroll
        for (int p = 0; p < 2; p++) {
            float v[4];
#pragma unroll
            for (int n = 0; n < 4; n++)
                v[n] = 0.5f * (c[2 * p][n] + c[2 * p + 1][n]) + bv[n];
            int pr = (bm >> 1) + ty * 2 + p;
            *(float4*)&C[(size_t)pr * Nc + bn + tx * 4] = make_float4(v[0], v[1], v[2], v[3]);
        }
    } else {
#pragma unroll
        for (int m = 0; m < 4; m++) {
            float v[4];
#pragma unroll
            for (int n = 0; n < 4; n++) {
                v[n] = c[m][n] + bv[n];
                if (mode == 1) v[n] = fmaxf(v[n], 0.f);
            }
            int row = bm + ty * 4 + m;
            *(float4*)&C[(size_t)row * Nc + bn + tx * 4] = make_float4(v[0], v[1], v[2], v[3]);
        }
    }
}

// ---------------------------------------------------------------------------
// Split-K reduction: sums S partial planes (fixed z order => deterministic),
// applies bias / relu / pairwise-pool.
// ---------------------------------------------------------------------------
__global__ void reduce_k(const float* __restrict__ part, const float* __restrict__ bias,
                         float* __restrict__ C, int M, int Nc, int S, int mode)
{
    int idx = blockIdx.x * blockDim.x + threadIdx.x;
    const int nc4 = Nc >> 2;
    const int rows = (mode == 2) ? (M >> 1) : M;
    if (idx >= rows * nc4) return;
    int r = idx / nc4, c4 = idx - r * nc4;
    const size_t plane = (size_t)M * Nc;

    float4 s = make_float4(0.f, 0.f, 0.f, 0.f);
    if (mode == 2) {
        for (int z = 0; z < S; z++) {
            float4 a = *(const float4*)&part[z * plane + (size_t)(2 * r)     * Nc + c4 * 4];
            float4 b = *(const float4*)&part[z * plane + (size_t)(2 * r + 1) * Nc + c4 * 4];
            s.x += a.x + b.x; s.y += a.y + b.y; s.z += a.z + b.z; s.w += a.w + b.w;
        }
        s.x *= 0.5f; s.y *= 0.5f; s.z *= 0.5f; s.w *= 0.5f;
    } else {
        for (int z = 0; z < S; z++) {
            float4 a = *(const float4*)&part[z * plane + (size_t)r * Nc + c4 * 4];
            s.x += a.x; s.y += a.y; s.z += a.z; s.w += a.w;
        }
    }
    float4 bb = make_float4(0.f, 0.f, 0.f, 0.f);
    if (bias) bb = ((const float4*)bias)[c4];
    s.x += bb.x; s.y += bb.y; s.z += bb.z; s.w += bb.w;
    if (mode == 1) {
        s.x = fmaxf(s.x, 0.f); s.y = fmaxf(s.y, 0.f);
        s.z = fmaxf(s.z, 0.f); s.w = fmaxf(s.w, 0.f);
    }
    *(float4*)&C[(size_t)r * Nc + c4 * 4] = s;
}

// ---------------------------------------------------------------------------
// Multi-head attention: qkv [B, Nl, 3*DIM] -> out [B, Nl, DIM]
// ---------------------------------------------------------------------------
__global__ void attn_k(const float* __restrict__ qkv, float* __restrict__ out, int Nl)
{
    extern __shared__ float sm[];
    float* Ks  = sm;                    // Nl*68
    float* Vs  = Ks + Nl * 68;          // Nl*68
    float* qs  = Vs + Nl * 68;          // 8*64
    float* psd = qs + 8 * 64;           // 8 * 2*Nl (duplicated probs)

    const int b = blockIdx.x >> 3, h = blockIdx.x & 7;
    const float* base = qkv + (size_t)b * Nl * (3 * DIM);
    const int tid = threadIdx.x, warp = tid >> 5, lane = tid & 31;

    for (int idx = tid; idx < Nl * 16; idx += 256) {
        int n = idx >> 4, dv = idx & 15;
        const float* rowp = base + (size_t)n * (3 * DIM) + h * 64 + dv * 4;
        *(float4*)&Ks[n * 68 + dv * 4] = *(const float4*)(rowp + DIM);
        *(float4*)&Vs[n * 68 + dv * 4] = *(const float4*)(rowp + 2 * DIM);
    }
    __syncthreads();

    const int jcnt = Nl >> 5;
    for (int r = blockIdx.y * 8 + warp; r < Nl; r += 8 * gridDim.y) {
        if (lane < 16)
            ((float4*)&qs[warp * 64])[lane] =
                *(const float4*)&base[(size_t)r * (3 * DIM) + h * 64 + lane * 4];
        __syncwarp();

        const ulonglong2* qr = (const ulonglong2*)&qs[warp * 64];
        float sv[8];
        float mx = -1e30f;
        for (int t = 0; t < jcnt; t++) {
            int j = t * 32 + lane;
            const ulonglong2* kr = (const ulonglong2*)&Ks[j * 68];
            u64 p0 = 0ull, p1 = 0ull;
#pragma unroll
            for (int i = 0; i < 16; i += 2) {
                ulonglong2 q0 = qr[i],     k0 = kr[i];
                ulonglong2 q1 = qr[i + 1], k1 = kr[i + 1];
                ffma2(p0, q0.x, k0.x); ffma2(p1, q0.y, k0.y);
                ffma2(p0, q1.x, k1.x); ffma2(p1, q1.y, k1.y);
            }
            float a0, a1, a2, a3;
            unpack2(p0, a0, a1); unpack2(p1, a2, a3);
            float s = (a0 + a1 + a2 + a3) * 0.125f;
            sv[t] = s;
            mx = fmaxf(mx, s);
        }
#pragma unroll
        for (int o = 16; o; o >>= 1) mx = fmaxf(mx, __shfl_xor_sync(0xffffffffu, mx, o));
        float sum = 0.f;
        for (int t = 0; t < jcnt; t++) { float e = expf(sv[t] - mx); sv[t] = e; sum += e; }
#pragma unroll
        for (int o = 16; o; o >>= 1) sum += __shfl_xor_sync(0xffffffffu, sum, o);
        float inv = 1.f / sum;
        for (int t = 0; t < jcnt; t++) {
            int j = t * 32 + lane;
            float p = sv[t] * inv;
            *(float2*)&psd[warp * 2 * Nl + 2 * j] = make_float2(p, p);
        }
        __syncwarp();

        u64 av[4] = {0ull, 0ull, 0ull, 0ull};
        const float* pw = &psd[warp * 2 * Nl];
        for (int j = 0; j < Nl; j += 4) {
            ffma2(av[0], *(const u64*)&pw[2 * j],     *(const u64*)&Vs[(j)     * 68 + 2 * lane]);
            ffma2(av[1], *(const u64*)&pw[2 * j + 2], *(const u64*)&Vs[(j + 1) * 68 + 2 * lane]);
            ffma2(av[2], *(const u64*)&pw[2 * j + 4], *(const u64*)&Vs[(j + 2) * 68 + 2 * lane]);
            ffma2(av[3], *(const u64*)&pw[2 * j + 6], *(const u64*)&Vs[(j + 3) * 68 + 2 * lane]);
        }
        float l0, h0, l1, h1, l2, h2, l3, h3;
        unpack2(av[0], l0, h0); unpack2(av[1], l1, h1);
        unpack2(av[2], l2, h2); unpack2(av[3], l3, h3);
        float e0 = (l0 + l1) + (l2 + l3);
        float e1 = (h0 + h1) + (h2 + h3);
        *(float2*)&out[((size_t)b * Nl + r) * DIM + h * 64 + 2 * lane] = make_float2(e0, e1);
        __syncwarp();
    }
}

// ---------------------------------------------------------------------------
// Upsample + concat (float4)
// ---------------------------------------------------------------------------
__global__ void concat_k(const float* __restrict__ l0, const float* __restrict__ l1,
                         const float* __restrict__ l2, float* __restrict__ cat)
{
    int idx4 = blockIdx.x * blockDim.x + threadIdx.x;
    const int total4 = BB * NNODE * 3 * DIM / 4;
    if (idx4 >= total4) return;
    int c4 = idx4 % (3 * DIM / 4);
    int n  = (idx4 / (3 * DIM / 4)) % NNODE;
    int b  = idx4 / ((3 * DIM / 4) * NNODE);
    int col = c4 * 4, l = col >> 9, d = col & 511;
    const float* src = (l == 0) ? l0 : (l == 1) ? l1 : l2;
    int Nl = NNODE >> l;
    ((float4*)cat)[idx4] = *(const float4*)&src[((size_t)b * Nl + (n >> l)) * DIM + d];
}

// ---------------------------------------------------------------------------
// LayerNorm over last dim (512)
// ---------------------------------------------------------------------------
__global__ void ln_k(const float* __restrict__ in, const float* __restrict__ g,
                     const float* __restrict__ bta, float* __restrict__ out)
{
    const int row = blockIdx.x, t = threadIdx.x;
    const int warp = t >> 5, lane = t & 31;
    float4 v = ((const float4*)(in + (size_t)row * DIM))[t];
    __shared__ float red[4];

    float s = v.x + v.y + v.z + v.w;
#pragma unroll
    for (int o = 16; o; o >>= 1) s += __shfl_xor_sync(0xffffffffu, s, o);
    if (lane == 0) red[warp] = s;
    __syncthreads();
    float mean = (red[0] + red[1] + red[2] + red[3]) * (1.f / DIM);
    __syncthreads();

    float dx = v.x - mean, dy = v.y - mean, dz = v.z - mean, dw = v.w - mean;
    float s2 = dx * dx + dy * dy + dz * dz + dw * dw;
#pragma unroll
    for (int o = 16; o; o >>= 1) s2 += __shfl_xor_sync(0xffffffffu, s2, o);
    if (lane == 0) red[warp] = s2;
    __syncthreads();
    float var = (red[0] + red[1] + red[2] + red[3]) * (1.f / DIM);
    float inv = 1.f / sqrtf(var + 1e-5f);

    float4 gv = ((const float4*)g)[t];
    float4 bv = ((const float4*)bta)[t];
    float4 r;
    r.x = dx * inv * gv.x + bv.x;
    r.y = dy * inv * gv.y + bv.y;
    r.z = dz * inv * gv.z + bv.z;
    r.w = dw * inv * gv.w + bv.w;
    ((float4*)(out + (size_t)row * DIM))[t] = r;
}

// ---------------------------------------------------------------------------
// Repack We1[1024,512] -> wef[512,1024] (hi|hj column blocks) + fused bias
// ---------------------------------------------------------------------------
__global__ void repack_k(const float* __restrict__ We1, const float* __restrict__ be1,
                         float* __restrict__ wef, float* __restrict__ bef)
{
    int idx = blockIdx.x * blockDim.x + threadIdx.x;
    if (idx < DIM * 2 * DIM) {
        int k = idx >> 10, n = idx & 1023;
        wef[idx] = (n < DIM) ? We1[(size_t)k * DIM + n]
                             : We1[(size_t)(DIM + k) * DIM + (n - DIM)];
    }
    if (idx < 2 * DIM) bef[idx] = (idx < DIM) ? 0.f : be1[idx - DIM];
}

// ---------------------------------------------------------------------------
// Edge scores from merged ef buffer (row stride 1024: [hi | hj]).
// ---------------------------------------------------------------------------
__global__ void scores_k(const float* __restrict__ ef, const float* __restrict__ w2,
                         float* __restrict__ sc)
{
    __shared__ float His[16][68];
    __shared__ float Hjs[16][36];
    __shared__ float W2s[16];
    const int b = blockIdx.z;
    const int i0 = blockIdx.y * 64, j0 = blockIdx.x * 32;
    const int tid = threadIdx.x;
    const int tx = tid & 15, ty = tid >> 4;
    const float* hib = ef + ((size_t)b * NNODE + i0) * (2 * DIM);
    const float* hjb = ef + ((size_t)b * NNODE + j0) * (2 * DIM) + DIM;

    float acc[4][2];
#pragma unroll
    for (int i = 0; i < 4; i++) { acc[i][0] = 0.f; acc[i][1] = 0.f; }

    const int ir = tid >> 2, ic = tid & 3;
    const int jr = tid >> 3, jc = tid & 7;

    for (int k0 = 0; k0 < DIM; k0 += 16) {
        float4 a = *(const float4*)&hib[(size_t)ir * (2 * DIM) + k0 + ic * 4];
        His[ic * 4 + 0][ir] = a.x; His[ic * 4 + 1][ir] = a.y;
        His[ic * 4 + 2][ir] = a.z; His[ic * 4 + 3][ir] = a.w;
        float2 c = *(const float2*)&hjb[(size_t)jr * (2 * DIM) + k0 + jc * 2];
        Hjs[jc * 2 + 0][jr] = c.x; Hjs[jc * 2 + 1][jr] = c.y;
        if (tid < 16) W2s[tid] = w2[k0 + tid];
        __syncthreads();
#pragma unroll
        for (int kk = 0; kk < 16; kk++) {
            float4 h4 = *(const float4*)&His[kk][ty * 4];
            float2 j2 = *(const float2*)&Hjs[kk][tx * 2];
            float w = W2s[kk];
            float hv[4] = {h4.x, h4.y, h4.z, h4.w};
#pragma unroll
            for (int i = 0; i < 4; i++) {
                acc[i][0] += fmaxf(hv[i] + j2.x, 0.f) * w;
                acc[i][1] += fmaxf(hv[i] + j2.y, 0.f) * w;
            }
        }
        __syncthreads();
    }

#pragma unroll
    for (int i = 0; i < 4; i++) {
        int gi = i0 + ty * 4 + i;
#pragma unroll
        for (int j = 0; j < 2; j++) {
            int gj = j0 + tx * 2 + j;
            sc[((size_t)b * NNODE + gi) * NNODE + gj] = (gi == gj) ? -1e30f : acc[i][j];
        }
    }
}

// ---------------------------------------------------------------------------
// Top-k (k=25) per row, warp per row; zeroes its row first.
// ---------------------------------------------------------------------------
__global__ void topk_k(const float* __restrict__ sc, float* __restrict__ adj)
{
    const int warp = threadIdx.x >> 5, lane = threadIdx.x & 31;
    const int row = blockIdx.x * 8 + warp;
    const float* s = sc + (size_t)row * NNODE;
    float v[8];
#pragma unroll
    for (int t = 0; t < 8; t++) v[t] = s[t * 32 + lane];
    float* arow = adj + (size_t)row * NNODE;
#pragma unroll
    for (int t = 0; t < 8; t++) arow[t * 32 + lane] = 0.f;
    __syncwarp();

    for (int it = 0; it < KSP; it++) {
        float bv = -3e38f; int bi = 0;
#pragma unroll
        for (int t = 0; t < 8; t++) {
            int j = t * 32 + lane;
            if (v[t] > bv) { bv = v[t]; bi = j; }
        }
#pragma unroll
        for (int o = 16; o; o >>= 1) {
            float ov = __shfl_xor_sync(0xffffffffu, bv, o);
            int   oi = __shfl_xor_sync(0xffffffffu, bi, o);
            if (ov > bv || (ov == bv && oi < bi)) { bv = ov; bi = oi; }
        }
        if (lane == (bi & 31)) v[bi >> 5] = -3e38f;
        if (lane == 0) arow[bi] = 1.0f;
        __syncwarp();
    }
}

// ---------------------------------------------------------------------------
// Host orchestration
// ---------------------------------------------------------------------------
static float* symaddr(const void* s)
{
    void* p = nullptr;
    cudaGetSymbolAddress(&p, s);
    return (float*)p;
}

static float* s_part = nullptr;

static void gemm(const float* A, const float* W, const float* bias, float* C,
                 int M, int K, int Nc, int mode, int S)
{
    sgemm_k<<<dim3(Nc / 64, M / 64, S), 256>>>(A, W, bias, C, M, K, Nc, mode, s_part);
    if (S > 1) {
        int rows = (mode == 2) ? M / 2 : M;
        int total = rows * (Nc / 4);
        reduce_k<<<(total + 255) / 256, 256>>>(s_part, bias, C, M, Nc, S, mode);
    }
}

extern "C" void kernel_launch(void* const* d_in, const int* in_sizes, int n_in,
                              void* d_out, int out_size)
{
    const float* x      = (const float*)d_in[0];
    const float* Wqkv   = (const float*)d_in[2];
    const float* bqkv   = (const float*)d_in[3];
    const float* Wo     = (const float*)d_in[4];
    const float* bo     = (const float*)d_in[5];
    const float* Wp1    = (const float*)d_in[6];
    const float* bp1    = (const float*)d_in[7];
    const float* Wp2    = (const float*)d_in[8];
    const float* bp2    = (const float*)d_in[9];
    const float* Wfuse  = (const float*)d_in[10];
    const float* bfuse  = (const float*)d_in[11];
    const float* ln_g   = (const float*)d_in[12];
    const float* ln_b   = (const float*)d_in[13];
    const float* We1    = (const float*)d_in[14];
    const float* be1    = (const float*)d_in[15];
    const float* We2    = (const float*)d_in[16];
    const float* Ws_qkv = (const float*)d_in[18];
    const float* bs_qkv = (const float*)d_in[19];
    const float* Ws_o   = (const float*)d_in[20];
    const float* bs_o   = (const float*)d_in[21];

    float* out_att = (float*)d_out;                      // [B,N,D]
    float* out_adj = out_att + (size_t)BB * NNODE * DIM; // [B,N,N]

    float* cur  = symaddr(g_cur);
    float* qkv  = symaddr(g_qkv);
    float* atto = symaddr(g_atto);
    float* lvl0 = symaddr(g_lvl0);
    float* lvl1 = symaddr(g_lvl1);
    float* lvl2 = symaddr(g_lvl2);
    float* t1   = symaddr(g_t1);
    float* pbuf = symaddr(g_p);
    float* cat  = symaddr(g_cat);
    float* hier = symaddr(g_hier);
    float* ef   = symaddr(g_ef);
    float* wef  = symaddr(g_wef);
    float* bef  = symaddr(g_bef);
    float* sc   = symaddr(g_sc);
    s_part      = symaddr(g_part);

    cudaFuncSetAttribute(attn_k, cudaFuncAttributeMaxDynamicSharedMemorySize, 160000);

    float* lvls[3] = {lvl0, lvl1, lvl2};
    const float* curp = x;

    // repack We1 early (independent of everything else)
    repack_k<<<(DIM * 2 * DIM + 255) / 256, 256>>>(We1, be1, wef, bef);

    // per-level split factors (target grid >= ~256 CTAs; K/S stays mult of 16)
    const int qkvS[3] = {1, 2, 4};
    const int woS [3] = {4, 4, 8};
    const int wp1S[3] = {4, 8, 0};
    const int wp2S[3] = {4, 4, 0};

    for (int l = 0; l < 3; l++) {
        const int Nl = NNODE >> l;
        const int M  = BB * Nl;
        gemm(curp, Wqkv + (size_t)l * DIM * 3 * DIM, bqkv + (size_t)l * 3 * DIM,
             qkv, M, DIM, 3 * DIM, 0, qkvS[l]);
        size_t smem = (size_t)(Nl * 68 * 2 + 8 * 64 + 8 * 2 * Nl) * sizeof(float);
        attn_k<<<dim3(BB * NH, 4), 256, smem>>>(qkv, atto, Nl);
        gemm(atto, Wo + (size_t)l * DIM * DIM, bo + (size_t)l * DIM,
             lvls[l], M, DIM, DIM, 0, woS[l]);
        if (l < 2) {
            gemm(lvls[l], Wp1 + (size_t)l * DIM * (DIM / 2), bp1 + (size_t)l * (DIM / 2),
                 t1, M, DIM, DIM / 2, 1, wp1S[l]);
            // Wp2 with fused pairwise pooling -> cur (M/2 rows)
            gemm(t1, Wp2 + (size_t)l * (DIM / 2) * DIM, bp2 + (size_t)l * DIM,
                 cur, M, DIM / 2, DIM, 2, wp2S[l]);
            curp = cur;
        }
    }

    // fuse: concat upsampled levels -> GEMM(relu) -> LayerNorm
    {
        const int total4 = BB * NNODE * 3 * DIM / 4;
        concat_k<<<(total4 + 255) / 256, 256>>>(lvl0, lvl1, lvl2, cat);
        gemm(cat, Wfuse, bfuse, pbuf, BB * NNODE, 3 * DIM, DIM, 1, 4);
        ln_k<<<BB * NNODE, 128>>>(pbuf, ln_g, ln_b, hier);
    }

    // sparse edge scoring + top-k (merged hi|hj GEMM)
    {
        gemm(hier, wef, bef, ef, BB * NNODE, DIM, 2 * DIM, 0, 2);
        scores_k<<<dim3(NNODE / 32, NNODE / 64, BB), 256>>>(ef, We2, sc);
        topk_k<<<BB * NNODE / 8, 256>>>(sc, out_adj);
    }

    // final MHA on hier -> attended output
    {
        const int M = BB * NNODE;
        gemm(hier, Ws_qkv, bs_qkv, qkv, M, DIM, 3 * DIM, 0, 1);
        size_t smem = (size_t)(NNODE * 68 * 2 + 8 * 64 + 8 * 2 * NNODE) * sizeof(float);
        attn_k<<<dim3(BB * NH, 4), 256, smem>>>(qkv, atto, NNODE);
        gemm(atto, Ws_o, bs_o, out_att, M, DIM, DIM, 0, 4);
    }
}

// round 9
// speedup vs baseline: 1.9605x; 1.0655x over previous
#include <cuda_runtime.h>
#include <math.h>

#define BB 4
#define NNODE 256
#define DIM 512
#define NH 8
#define KSP 25

// ---------------------------------------------------------------------------
// Scratch (no allocations allowed anywhere)
// ---------------------------------------------------------------------------
__device__ float g_cur [BB*NNODE*DIM];
__device__ float g_qkv [BB*NNODE*3*DIM];
__device__ float g_atto[BB*NNODE*DIM];
__device__ float g_lvl0[BB*NNODE*DIM];
__device__ float g_lvl1[BB*(NNODE/2)*DIM];
__device__ float g_lvl2[BB*(NNODE/4)*DIM];
__device__ float g_t1  [BB*NNODE*(DIM/2)];
__device__ float g_p   [BB*NNODE*DIM];
__device__ float g_cat [BB*NNODE*3*DIM];
__device__ float g_hier[BB*NNODE*DIM];
__device__ float g_ef  [BB*NNODE*2*DIM];
__device__ float g_wef [DIM*2*DIM];
__device__ float g_bef [2*DIM];
__device__ float g_sc  [BB*NNODE*NNODE];
__device__ float g_part[4*1024*1024];   // split-K partials (16 MB)

typedef unsigned long long u64;

__device__ __forceinline__ void ffma2(u64& d, u64 a, u64 b) {
    asm("fma.rn.f32x2 %0, %1, %2, %0;" : "+l"(d) : "l"(a), "l"(b));
}
__device__ __forceinline__ void unpack2(u64 v, float& lo, float& hi) {
    asm("mov.b64 {%0, %1}, %2;" : "=f"(lo), "=f"(hi) : "l"(v));
}

// ---------------------------------------------------------------------------
// SGEMM: C[M,Nc] = A[M,K] @ W[K,Nc] (+bias) (+relu / pool)
// 128 threads (4 warps), 128x64 tile, 8Mx8N per thread, BK=16, double-buffered.
// f32x2 accumulators pair adjacent N. A stored DUPLICATED (a,a) in shared
// (broadcast operand, cheap); B plain. Per kk: 6 LDS feed 32 FFMA2.
// Split-K via gridDim.z; partials are raw planes finished by reduce_k.
// mode: 0 = bias, 1 = bias+relu, 2 = pairwise-pool rows (0.5*(r0+r1)+bias)
// ---------------------------------------------------------------------------
__global__ void __launch_bounds__(128)
sgemm_k(const float* __restrict__ A, const float* __restrict__ W,
        const float* __restrict__ bias, float* __restrict__ C,
        int M, int K, int Nc, int mode, float* __restrict__ part)
{
    __shared__ float Ad[2][16][264];   // duplicated A: Ad[k][2r],[2r+1] = A[r]
    __shared__ float Bs[2][16][64];    // plain B tile

    const int S = gridDim.z, z = blockIdx.z;
    const int Ks = K / S;              // multiple of 16 by construction
    const int kbase = z * Ks;

    const int bm = blockIdx.y * 128, bn = blockIdx.x * 64;
    const int tid = threadIdx.x;
    const int ty = tid >> 3;        // 0..15 : rows ty*8 .. ty*8+7
    const int tx = tid & 7;         // 0..7  : cols tx*8 .. tx*8+7 (4 n-pairs)

    u64 acc[8][4];
#pragma unroll
    for (int i = 0; i < 8; i++)
#pragma unroll
        for (int j = 0; j < 4; j++) acc[i][j] = 0ull;

    const int nk = Ks >> 4;
    // A: thread tid owns global row bm+tid, loads its 16 k-values (4 float4)
    // B: f = tid + 128*i (i=0,1): k = f>>4, c4 = f&15
    float4 areg[4], breg[2];

#pragma unroll
    for (int i = 0; i < 4; i++)
        areg[i] = *(const float4*)&A[(size_t)(bm + tid) * K + kbase + i * 4];
#pragma unroll
    for (int i = 0; i < 2; i++) {
        int f = tid + 128 * i;
        breg[i] = *(const float4*)&W[(size_t)(kbase + (f >> 4)) * Nc + bn + (f & 15) * 4];
    }
#pragma unroll
    for (int i = 0; i < 4; i++) {
        *(float2*)&Ad[0][i * 4 + 0][2 * tid] = make_float2(areg[i].x, areg[i].x);
        *(float2*)&Ad[0][i * 4 + 1][2 * tid] = make_float2(areg[i].y, areg[i].y);
        *(float2*)&Ad[0][i * 4 + 2][2 * tid] = make_float2(areg[i].z, areg[i].z);
        *(float2*)&Ad[0][i * 4 + 3][2 * tid] = make_float2(areg[i].w, areg[i].w);
    }
#pragma unroll
    for (int i = 0; i < 2; i++) {
        int f = tid + 128 * i;
        *(float4*)&Bs[0][f >> 4][(f & 15) * 4] = breg[i];
    }
    __syncthreads();

    for (int k0 = 0; k0 < nk; k0++) {
        const int buf = k0 & 1;
        if (k0 + 1 < nk) {
            const int kb = kbase + ((k0 + 1) << 4);
#pragma unroll
            for (int i = 0; i < 4; i++)
                areg[i] = *(const float4*)&A[(size_t)(bm + tid) * K + kb + i * 4];
#pragma unroll
            for (int i = 0; i < 2; i++) {
                int f = tid + 128 * i;
                breg[i] = *(const float4*)&W[(size_t)(kb + (f >> 4)) * Nc + bn + (f & 15) * 4];
            }
        }
#pragma unroll
        for (int kk = 0; kk < 16; kk++) {
            ulonglong2 a0 = *(const ulonglong2*)&Ad[buf][kk][ty * 16];
            ulonglong2 a1 = *(const ulonglong2*)&Ad[buf][kk][ty * 16 + 4];
            ulonglong2 a2 = *(const ulonglong2*)&Ad[buf][kk][ty * 16 + 8];
            ulonglong2 a3 = *(const ulonglong2*)&Ad[buf][kk][ty * 16 + 12];
            ulonglong2 b0 = *(const ulonglong2*)&Bs[buf][kk][tx * 8];
            ulonglong2 b1 = *(const ulonglong2*)&Bs[buf][kk][tx * 8 + 4];
            u64 av[8] = {a0.x, a0.y, a1.x, a1.y, a2.x, a2.y, a3.x, a3.y};
            u64 bv[4] = {b0.x, b0.y, b1.x, b1.y};
#pragma unroll
            for (int m = 0; m < 8; m++) {
                ffma2(acc[m][0], av[m], bv[0]);
                ffma2(acc[m][1], av[m], bv[1]);
                ffma2(acc[m][2], av[m], bv[2]);
                ffma2(acc[m][3], av[m], bv[3]);
            }
        }
        if (k0 + 1 < nk) {
            const int nb = buf ^ 1;
#pragma unroll
            for (int i = 0; i < 4; i++) {
                *(float2*)&Ad[nb][i * 4 + 0][2 * tid] = make_float2(areg[i].x, areg[i].x);
                *(float2*)&Ad[nb][i * 4 + 1][2 * tid] = make_float2(areg[i].y, areg[i].y);
                *(float2*)&Ad[nb][i * 4 + 2][2 * tid] = make_float2(areg[i].z, areg[i].z);
                *(float2*)&Ad[nb][i * 4 + 3][2 * tid] = make_float2(areg[i].w, areg[i].w);
            }
#pragma unroll
            for (int i = 0; i < 2; i++) {
                int f = tid + 128 * i;
                *(float4*)&Bs[nb][f >> 4][(f & 15) * 4] = breg[i];
            }
        }
        __syncthreads();
    }

    float c[8][8];
#pragma unroll
    for (int m = 0; m < 8; m++) {
        unpack2(acc[m][0], c[m][0], c[m][1]);
        unpack2(acc[m][1], c[m][2], c[m][3]);
        unpack2(acc[m][2], c[m][4], c[m][5]);
        unpack2(acc[m][3], c[m][6], c[m][7]);
    }

    if (S > 1) {
        const size_t plane = (size_t)M * Nc;
#pragma unroll
        for (int m = 0; m < 8; m++) {
            int row = bm + ty * 8 + m;
            float* p = &part[z * plane + (size_t)row * Nc + bn + tx * 8];
            *(float4*)p       = make_float4(c[m][0], c[m][1], c[m][2], c[m][3]);
            *(float4*)(p + 4) = make_float4(c[m][4], c[m][5], c[m][6], c[m][7]);
        }
        return;
    }

    float bv8[8] = {0.f, 0.f, 0.f, 0.f, 0.f, 0.f, 0.f, 0.f};
    if (bias) {
        float4 b0 = *(const float4*)&bias[bn + tx * 8];
        float4 b1 = *(const float4*)&bias[bn + tx * 8 + 4];
        bv8[0] = b0.x; bv8[1] = b0.y; bv8[2] = b0.z; bv8[3] = b0.w;
        bv8[4] = b1.x; bv8[5] = b1.y; bv8[6] = b1.z; bv8[7] = b1.w;
    }

    if (mode == 2) {
#pragma unroll
        for (int p = 0; p < 4; p++) {
            float v[8];
#pragma unroll
            for (int n = 0; n < 8; n++)
                v[n] = 0.5f * (c[2 * p][n] + c[2 * p + 1][n]) + bv8[n];
            int pr = (bm >> 1) + ty * 4 + p;
            float* o = &C[(size_t)pr * Nc + bn + tx * 8];
            *(float4*)o       = make_float4(v[0], v[1], v[2], v[3]);
            *(float4*)(o + 4) = make_float4(v[4], v[5], v[6], v[7]);
        }
    } else {
#pragma unroll
        for (int m = 0; m < 8; m++) {
            float v[8];
#pragma unroll
            for (int n = 0; n < 8; n++) {
                v[n] = c[m][n] + bv8[n];
                if (mode == 1) v[n] = fmaxf(v[n], 0.f);
            }
            int row = bm + ty * 8 + m;
            float* o = &C[(size_t)row * Nc + bn + tx * 8];
            *(float4*)o       = make_float4(v[0], v[1], v[2], v[3]);
            *(float4*)(o + 4) = make_float4(v[4], v[5], v[6], v[7]);
        }
    }
}

// ---------------------------------------------------------------------------
// Split-K reduction: sums S partial planes (fixed z order => deterministic),
// applies bias / relu / pairwise-pool.
// ---------------------------------------------------------------------------
__global__ void reduce_k(const float* __restrict__ part, const float* __restrict__ bias,
                         float* __restrict__ C, int M, int Nc, int S, int mode)
{
    int idx = blockIdx.x * blockDim.x + threadIdx.x;
    const int nc4 = Nc >> 2;
    const int rows = (mode == 2) ? (M >> 1) : M;
    if (idx >= rows * nc4) return;
    int r = idx / nc4, c4 = idx - r * nc4;
    const size_t plane = (size_t)M * Nc;

    float4 s = make_float4(0.f, 0.f, 0.f, 0.f);
    if (mode == 2) {
        for (int z = 0; z < S; z++) {
            float4 a = *(const float4*)&part[z * plane + (size_t)(2 * r)     * Nc + c4 * 4];
            float4 b = *(const float4*)&part[z * plane + (size_t)(2 * r + 1) * Nc + c4 * 4];
            s.x += a.x + b.x; s.y += a.y + b.y; s.z += a.z + b.z; s.w += a.w + b.w;
        }
        s.x *= 0.5f; s.y *= 0.5f; s.z *= 0.5f; s.w *= 0.5f;
    } else {
        for (int z = 0; z < S; z++) {
            float4 a = *(const float4*)&part[z * plane + (size_t)r * Nc + c4 * 4];
            s.x += a.x; s.y += a.y; s.z += a.z; s.w += a.w;
        }
    }
    float4 bb = make_float4(0.f, 0.f, 0.f, 0.f);
    if (bias) bb = ((const float4*)bias)[c4];
    s.x += bb.x; s.y += bb.y; s.z += bb.z; s.w += bb.w;
    if (mode == 1) {
        s.x = fmaxf(s.x, 0.f); s.y = fmaxf(s.y, 0.f);
        s.z = fmaxf(s.z, 0.f); s.w = fmaxf(s.w, 0.f);
    }
    *(float4*)&C[(size_t)r * Nc + c4 * 4] = s;
}

// ---------------------------------------------------------------------------
// Multi-head attention: qkv [B, Nl, 3*DIM] -> out [B, Nl, DIM]
// ---------------------------------------------------------------------------
__global__ void attn_k(const float* __restrict__ qkv, float* __restrict__ out, int Nl)
{
    extern __shared__ float sm[];
    float* Ks  = sm;                    // Nl*68
    float* Vs  = Ks + Nl * 68;          // Nl*68
    float* qs  = Vs + Nl * 68;          // 8*64
    float* psd = qs + 8 * 64;           // 8 * 2*Nl (duplicated probs)

    const int b = blockIdx.x >> 3, h = blockIdx.x & 7;
    const float* base = qkv + (size_t)b * Nl * (3 * DIM);
    const int tid = threadIdx.x, warp = tid >> 5, lane = tid & 31;

    for (int idx = tid; idx < Nl * 16; idx += 256) {
        int n = idx >> 4, dv = idx & 15;
        const float* rowp = base + (size_t)n * (3 * DIM) + h * 64 + dv * 4;
        *(float4*)&Ks[n * 68 + dv * 4] = *(const float4*)(rowp + DIM);
        *(float4*)&Vs[n * 68 + dv * 4] = *(const float4*)(rowp + 2 * DIM);
    }
    __syncthreads();

    const int jcnt = Nl >> 5;
    for (int r = blockIdx.y * 8 + warp; r < Nl; r += 8 * gridDim.y) {
        if (lane < 16)
            ((float4*)&qs[warp * 64])[lane] =
                *(const float4*)&base[(size_t)r * (3 * DIM) + h * 64 + lane * 4];
        __syncwarp();

        const ulonglong2* qr = (const ulonglong2*)&qs[warp * 64];
        float sv[8];
        float mx = -1e30f;
        for (int t = 0; t < jcnt; t++) {
            int j = t * 32 + lane;
            const ulonglong2* kr = (const ulonglong2*)&Ks[j * 68];
            u64 p0 = 0ull, p1 = 0ull;
#pragma unroll
            for (int i = 0; i < 16; i += 2) {
                ulonglong2 q0 = qr[i],     k0 = kr[i];
                ulonglong2 q1 = qr[i + 1], k1 = kr[i + 1];
                ffma2(p0, q0.x, k0.x); ffma2(p1, q0.y, k0.y);
                ffma2(p0, q1.x, k1.x); ffma2(p1, q1.y, k1.y);
            }
            float a0, a1, a2, a3;
            unpack2(p0, a0, a1); unpack2(p1, a2, a3);
            float s = (a0 + a1 + a2 + a3) * 0.125f;
            sv[t] = s;
            mx = fmaxf(mx, s);
        }
#pragma unroll
        for (int o = 16; o; o >>= 1) mx = fmaxf(mx, __shfl_xor_sync(0xffffffffu, mx, o));
        float sum = 0.f;
        for (int t = 0; t < jcnt; t++) { float e = expf(sv[t] - mx); sv[t] = e; sum += e; }
#pragma unroll
        for (int o = 16; o; o >>= 1) sum += __shfl_xor_sync(0xffffffffu, sum, o);
        float inv = 1.f / sum;
        for (int t = 0; t < jcnt; t++) {
            int j = t * 32 + lane;
            float p = sv[t] * inv;
            *(float2*)&psd[warp * 2 * Nl + 2 * j] = make_float2(p, p);
        }
        __syncwarp();

        u64 av[4] = {0ull, 0ull, 0ull, 0ull};
        const float* pw = &psd[warp * 2 * Nl];
        for (int j = 0; j < Nl; j += 4) {
            ffma2(av[0], *(const u64*)&pw[2 * j],     *(const u64*)&Vs[(j)     * 68 + 2 * lane]);
            ffma2(av[1], *(const u64*)&pw[2 * j + 2], *(const u64*)&Vs[(j + 1) * 68 + 2 * lane]);
            ffma2(av[2], *(const u64*)&pw[2 * j + 4], *(const u64*)&Vs[(j + 2) * 68 + 2 * lane]);
            ffma2(av[3], *(const u64*)&pw[2 * j + 6], *(const u64*)&Vs[(j + 3) * 68 + 2 * lane]);
        }
        float l0, h0, l1, h1, l2, h2, l3, h3;
        unpack2(av[0], l0, h0); unpack2(av[1], l1, h1);
        unpack2(av[2], l2, h2); unpack2(av[3], l3, h3);
        float e0 = (l0 + l1) + (l2 + l3);
        float e1 = (h0 + h1) + (h2 + h3);
        *(float2*)&out[((size_t)b * Nl + r) * DIM + h * 64 + 2 * lane] = make_float2(e0, e1);
        __syncwarp();
    }
}

// ---------------------------------------------------------------------------
// Upsample + concat (float4)
// ---------------------------------------------------------------------------
__global__ void concat_k(const float* __restrict__ l0, const float* __restrict__ l1,
                         const float* __restrict__ l2, float* __restrict__ cat)
{
    int idx4 = blockIdx.x * blockDim.x + threadIdx.x;
    const int total4 = BB * NNODE * 3 * DIM / 4;
    if (idx4 >= total4) return;
    int c4 = idx4 % (3 * DIM / 4);
    int n  = (idx4 / (3 * DIM / 4)) % NNODE;
    int b  = idx4 / ((3 * DIM / 4) * NNODE);
    int col = c4 * 4, l = col >> 9, d = col & 511;
    const float* src = (l == 0) ? l0 : (l == 1) ? l1 : l2;
    int Nl = NNODE >> l;
    ((float4*)cat)[idx4] = *(const float4*)&src[((size_t)b * Nl + (n >> l)) * DIM + d];
}

// ---------------------------------------------------------------------------
// LayerNorm over last dim (512)
// ---------------------------------------------------------------------------
__global__ void ln_k(const float* __restrict__ in, const float* __restrict__ g,
                     const float* __restrict__ bta, float* __restrict__ out)
{
    const int row = blockIdx.x, t = threadIdx.x;
    const int warp = t >> 5, lane = t & 31;
    float4 v = ((const float4*)(in + (size_t)row * DIM))[t];
    __shared__ float red[4];

    float s = v.x + v.y + v.z + v.w;
#pragma unroll
    for (int o = 16; o; o >>= 1) s += __shfl_xor_sync(0xffffffffu, s, o);
    if (lane == 0) red[warp] = s;
    __syncthreads();
    float mean = (red[0] + red[1] + red[2] + red[3]) * (1.f / DIM);
    __syncthreads();

    float dx = v.x - mean, dy = v.y - mean, dz = v.z - mean, dw = v.w - mean;
    float s2 = dx * dx + dy * dy + dz * dz + dw * dw;
#pragma unroll
    for (int o = 16; o; o >>= 1) s2 += __shfl_xor_sync(0xffffffffu, s2, o);
    if (lane == 0) red[warp] = s2;
    __syncthreads();
    float var = (red[0] + red[1] + red[2] + red[3]) * (1.f / DIM);
    float inv = 1.f / sqrtf(var + 1e-5f);

    float4 gv = ((const float4*)g)[t];
    float4 bv = ((const float4*)bta)[t];
    float4 r;
    r.x = dx * inv * gv.x + bv.x;
    r.y = dy * inv * gv.y + bv.y;
    r.z = dz * inv * gv.z + bv.z;
    r.w = dw * inv * gv.w + bv.w;
    ((float4*)(out + (size_t)row * DIM))[t] = r;
}

// ---------------------------------------------------------------------------
// Repack We1[1024,512] -> wef[512,1024] (hi|hj column blocks) + fused bias
// ---------------------------------------------------------------------------
__global__ void repack_k(const float* __restrict__ We1, const float* __restrict__ be1,
                         float* __restrict__ wef, float* __restrict__ bef)
{
    int idx = blockIdx.x * blockDim.x + threadIdx.x;
    if (idx < DIM * 2 * DIM) {
        int k = idx >> 10, n = idx & 1023;
        wef[idx] = (n < DIM) ? We1[(size_t)k * DIM + n]
                             : We1[(size_t)(DIM + k) * DIM + (n - DIM)];
    }
    if (idx < 2 * DIM) bef[idx] = (idx < DIM) ? 0.f : be1[idx - DIM];
}

// ---------------------------------------------------------------------------
// Edge scores from merged ef buffer (row stride 1024: [hi | hj]).
// ---------------------------------------------------------------------------
__global__ void scores_k(const float* __restrict__ ef, const float* __restrict__ w2,
                         float* __restrict__ sc)
{
    __shared__ float His[16][68];
    __shared__ float Hjs[16][36];
    __shared__ float W2s[16];
    const int b = blockIdx.z;
    const int i0 = blockIdx.y * 64, j0 = blockIdx.x * 32;
    const int tid = threadIdx.x;
    const int tx = tid & 15, ty = tid >> 4;
    const float* hib = ef + ((size_t)b * NNODE + i0) * (2 * DIM);
    const float* hjb = ef + ((size_t)b * NNODE + j0) * (2 * DIM) + DIM;

    float acc[4][2];
#pragma unroll
    for (int i = 0; i < 4; i++) { acc[i][0] = 0.f; acc[i][1] = 0.f; }

    const int ir = tid >> 2, ic = tid & 3;
    const int jr = tid >> 3, jc = tid & 7;

    for (int k0 = 0; k0 < DIM; k0 += 16) {
        float4 a = *(const float4*)&hib[(size_t)ir * (2 * DIM) + k0 + ic * 4];
        His[ic * 4 + 0][ir] = a.x; His[ic * 4 + 1][ir] = a.y;
        His[ic * 4 + 2][ir] = a.z; His[ic * 4 + 3][ir] = a.w;
        float2 c = *(const float2*)&hjb[(size_t)jr * (2 * DIM) + k0 + jc * 2];
        Hjs[jc * 2 + 0][jr] = c.x; Hjs[jc * 2 + 1][jr] = c.y;
        if (tid < 16) W2s[tid] = w2[k0 + tid];
        __syncthreads();
#pragma unroll
        for (int kk = 0; kk < 16; kk++) {
            float4 h4 = *(const float4*)&His[kk][ty * 4];
            float2 j2 = *(const float2*)&Hjs[kk][tx * 2];
            float w = W2s[kk];
            float hv[4] = {h4.x, h4.y, h4.z, h4.w};
#pragma unroll
            for (int i = 0; i < 4; i++) {
                acc[i][0] += fmaxf(hv[i] + j2.x, 0.f) * w;
                acc[i][1] += fmaxf(hv[i] + j2.y, 0.f) * w;
            }
        }
        __syncthreads();
    }

#pragma unroll
    for (int i = 0; i < 4; i++) {
        int gi = i0 + ty * 4 + i;
#pragma unroll
        for (int j = 0; j < 2; j++) {
            int gj = j0 + tx * 2 + j;
            sc[((size_t)b * NNODE + gi) * NNODE + gj] = (gi == gj) ? -1e30f : acc[i][j];
        }
    }
}

// ---------------------------------------------------------------------------
// Top-k (k=25) per row, warp per row; zeroes its row first.
// ---------------------------------------------------------------------------
__global__ void topk_k(const float* __restrict__ sc, float* __restrict__ adj)
{
    const int warp = threadIdx.x >> 5, lane = threadIdx.x & 31;
    const int row = blockIdx.x * 8 + warp;
    const float* s = sc + (size_t)row * NNODE;
    float v[8];
#pragma unroll
    for (int t = 0; t < 8; t++) v[t] = s[t * 32 + lane];
    float* arow = adj + (size_t)row * NNODE;
#pragma unroll
    for (int t = 0; t < 8; t++) arow[t * 32 + lane] = 0.f;
    __syncwarp();

    for (int it = 0; it < KSP; it++) {
        float bv = -3e38f; int bi = 0;
#pragma unroll
        for (int t = 0; t < 8; t++) {
            int j = t * 32 + lane;
            if (v[t] > bv) { bv = v[t]; bi = j; }
        }
#pragma unroll
        for (int o = 16; o; o >>= 1) {
            float ov = __shfl_xor_sync(0xffffffffu, bv, o);
            int   oi = __shfl_xor_sync(0xffffffffu, bi, o);
            if (ov > bv || (ov == bv && oi < bi)) { bv = ov; bi = oi; }
        }
        if (lane == (bi & 31)) v[bi >> 5] = -3e38f;
        if (lane == 0) arow[bi] = 1.0f;
        __syncwarp();
    }
}

// ---------------------------------------------------------------------------
// Host orchestration
// ---------------------------------------------------------------------------
static float* symaddr(const void* s)
{
    void* p = nullptr;
    cudaGetSymbolAddress(&p, s);
    return (float*)p;
}

static float* s_part = nullptr;

static void gemm(const float* A, const float* W, const float* bias, float* C,
                 int M, int K, int Nc, int mode, int S)
{
    sgemm_k<<<dim3(Nc / 64, M / 128, S), 128>>>(A, W, bias, C, M, K, Nc, mode, s_part);
    if (S > 1) {
        int rows = (mode == 2) ? M / 2 : M;
        int total = rows * (Nc / 4);
        reduce_k<<<(total + 255) / 256, 256>>>(s_part, bias, C, M, Nc, S, mode);
    }
}

extern "C" void kernel_launch(void* const* d_in, const int* in_sizes, int n_in,
                              void* d_out, int out_size)
{
    const float* x      = (const float*)d_in[0];
    const float* Wqkv   = (const float*)d_in[2];
    const float* bqkv   = (const float*)d_in[3];
    const float* Wo     = (const float*)d_in[4];
    const float* bo     = (const float*)d_in[5];
    const float* Wp1    = (const float*)d_in[6];
    const float* bp1    = (const float*)d_in[7];
    const float* Wp2    = (const float*)d_in[8];
    const float* bp2    = (const float*)d_in[9];
    const float* Wfuse  = (const float*)d_in[10];
    const float* bfuse  = (const float*)d_in[11];
    const float* ln_g   = (const float*)d_in[12];
    const float* ln_b   = (const float*)d_in[13];
    const float* We1    = (const float*)d_in[14];
    const float* be1    = (const float*)d_in[15];
    const float* We2    = (const float*)d_in[16];
    const float* Ws_qkv = (const float*)d_in[18];
    const float* bs_qkv = (const float*)d_in[19];
    const float* Ws_o   = (const float*)d_in[20];
    const float* bs_o   = (const float*)d_in[21];

    float* out_att = (float*)d_out;                      // [B,N,D]
    float* out_adj = out_att + (size_t)BB * NNODE * DIM; // [B,N,N]

    float* cur  = symaddr(g_cur);
    float* qkv  = symaddr(g_qkv);
    float* atto = symaddr(g_atto);
    float* lvl0 = symaddr(g_lvl0);
    float* lvl1 = symaddr(g_lvl1);
    float* lvl2 = symaddr(g_lvl2);
    float* t1   = symaddr(g_t1);
    float* pbuf = symaddr(g_p);
    float* cat  = symaddr(g_cat);
    float* hier = symaddr(g_hier);
    float* ef   = symaddr(g_ef);
    float* wef  = symaddr(g_wef);
    float* bef  = symaddr(g_bef);
    float* sc   = symaddr(g_sc);
    s_part      = symaddr(g_part);

    cudaFuncSetAttribute(attn_k, cudaFuncAttributeMaxDynamicSharedMemorySize, 160000);

    float* lvls[3] = {lvl0, lvl1, lvl2};
    const float* curp = x;

    // repack We1 early (independent of everything else)
    repack_k<<<(DIM * 2 * DIM + 255) / 256, 256>>>(We1, be1, wef, bef);

    // split factors tuned for 128-row tiles: grid >= ~256 CTAs, K/S mult of 16
    const int qkvS[3] = {2, 4, 8};
    const int woS [3] = {4, 8, 8};
    const int wp1S[3] = {8, 16, 0};
    const int wp2S[3] = {4, 8, 0};

    for (int l = 0; l < 3; l++) {
        const int Nl = NNODE >> l;
        const int M  = BB * Nl;
        gemm(curp, Wqkv + (size_t)l * DIM * 3 * DIM, bqkv + (size_t)l * 3 * DIM,
             qkv, M, DIM, 3 * DIM, 0, qkvS[l]);
        size_t smem = (size_t)(Nl * 68 * 2 + 8 * 64 + 8 * 2 * Nl) * sizeof(float);
        attn_k<<<dim3(BB * NH, 4), 256, smem>>>(qkv, atto, Nl);
        gemm(atto, Wo + (size_t)l * DIM * DIM, bo + (size_t)l * DIM,
             lvls[l], M, DIM, DIM, 0, woS[l]);
        if (l < 2) {
            gemm(lvls[l], Wp1 + (size_t)l * DIM * (DIM / 2), bp1 + (size_t)l * (DIM / 2),
                 t1, M, DIM, DIM / 2, 1, wp1S[l]);
            // Wp2 with fused pairwise pooling -> cur (M/2 rows)
            gemm(t1, Wp2 + (size_t)l * (DIM / 2) * DIM, bp2 + (size_t)l * DIM,
                 cur, M, DIM / 2, DIM, 2, wp2S[l]);
            curp = cur;
        }
    }

    // fuse: concat upsampled levels -> GEMM(relu) -> LayerNorm
    {
        const int total4 = BB * NNODE * 3 * DIM / 4;
        concat_k<<<(total4 + 255) / 256, 256>>>(lvl0, lvl1, lvl2, cat);
        gemm(cat, Wfuse, bfuse, pbuf, BB * NNODE, 3 * DIM, DIM, 1, 4);
        ln_k<<<BB * NNODE, 128>>>(pbuf, ln_g, ln_b, hier);
    }

    // sparse edge scoring + top-k (merged hi|hj GEMM)
    {
        gemm(hier, wef, bef, ef, BB * NNODE, DIM, 2 * DIM, 0, 2);
        scores_k<<<dim3(NNODE / 32, NNODE / 64, BB), 256>>>(ef, We2, sc);
        topk_k<<<BB * NNODE / 8, 256>>>(sc, out_adj);
    }

    // final MHA on hier -> attended output
    {
        const int M = BB * NNODE;
        gemm(hier, Ws_qkv, bs_qkv, qkv, M, DIM, 3 * DIM, 0, 2);
        size_t smem = (size_t)(NNODE * 68 * 2 + 8 * 64 + 8 * 2 * NNODE) * sizeof(float);
        attn_k<<<dim3(BB * NH, 4), 256, smem>>>(qkv, atto, NNODE);
        gemm(atto, Ws_o, bs_o, out_att, M, DIM, DIM, 0, 4);
    }
}

// round 11
// speedup vs baseline: 2.0264x; 1.0336x over previous
#include <cuda_runtime.h>
#include <math.h>

#define BB 4
#define NNODE 256
#define DIM 512
#define NH 8
#define KSP 25

// ---------------------------------------------------------------------------
// Scratch (no allocations allowed anywhere)
// ---------------------------------------------------------------------------
__device__ float g_cur [BB*NNODE*DIM];
__device__ float g_qkv [BB*NNODE*3*DIM];
__device__ float g_atto[BB*NNODE*DIM];
__device__ float g_lvl0[BB*NNODE*DIM];
__device__ float g_lvl1[BB*(NNODE/2)*DIM];
__device__ float g_lvl2[BB*(NNODE/4)*DIM];
__device__ float g_t1  [BB*NNODE*(DIM/2)];
__device__ float g_p   [BB*NNODE*DIM];
__device__ float g_cat [BB*NNODE*3*DIM];
__device__ float g_hier[BB*NNODE*DIM];
__device__ float g_ef  [BB*NNODE*2*DIM];
__device__ float g_wef [DIM*2*DIM];
__device__ float g_bef [2*DIM];
__device__ float g_sc  [BB*NNODE*NNODE];
__device__ float g_part[4*1024*1024];   // split-K partials (16 MB)

typedef unsigned long long u64;

__device__ __forceinline__ void ffma2(u64& d, u64 a, u64 b) {
    asm("fma.rn.f32x2 %0, %1, %2, %0;" : "+l"(d) : "l"(a), "l"(b));
}
__device__ __forceinline__ void unpack2(u64 v, float& lo, float& hi) {
    asm("mov.b64 {%0, %1}, %2;" : "=f"(lo), "=f"(hi) : "l"(v));
}

// ---------------------------------------------------------------------------
// SGEMM: C[M,Nc] = A[M,K] @ W[K,Nc] (+bias) (+relu / pool)
// 128 threads (4 warps), 128x64 tile, 8Mx8N per thread, BK=16, double-buffered.
// ---------------------------------------------------------------------------
__global__ void __launch_bounds__(128)
sgemm_k(const float* __restrict__ A, const float* __restrict__ W,
        const float* __restrict__ bias, float* __restrict__ C,
        int M, int K, int Nc, int mode, float* __restrict__ part)
{
    __shared__ float Ad[2][16][264];   // duplicated A: Ad[k][2r],[2r+1] = A[r]
    __shared__ float Bs[2][16][64];    // plain B tile

    const int S = gridDim.z, z = blockIdx.z;
    const int Ks = K / S;
    const int kbase = z * Ks;

    const int bm = blockIdx.y * 128, bn = blockIdx.x * 64;
    const int tid = threadIdx.x;
    const int ty = tid >> 3;
    const int tx = tid & 7;

    u64 acc[8][4];
#pragma unroll
    for (int i = 0; i < 8; i++)
#pragma unroll
        for (int j = 0; j < 4; j++) acc[i][j] = 0ull;

    const int nk = Ks >> 4;
    float4 areg[4], breg[2];

#pragma unroll
    for (int i = 0; i < 4; i++)
        areg[i] = *(const float4*)&A[(size_t)(bm + tid) * K + kbase + i * 4];
#pragma unroll
    for (int i = 0; i < 2; i++) {
        int f = tid + 128 * i;
        breg[i] = *(const float4*)&W[(size_t)(kbase + (f >> 4)) * Nc + bn + (f & 15) * 4];
    }
#pragma unroll
    for (int i = 0; i < 4; i++) {
        *(float2*)&Ad[0][i * 4 + 0][2 * tid] = make_float2(areg[i].x, areg[i].x);
        *(float2*)&Ad[0][i * 4 + 1][2 * tid] = make_float2(areg[i].y, areg[i].y);
        *(float2*)&Ad[0][i * 4 + 2][2 * tid] = make_float2(areg[i].z, areg[i].z);
        *(float2*)&Ad[0][i * 4 + 3][2 * tid] = make_float2(areg[i].w, areg[i].w);
    }
#pragma unroll
    for (int i = 0; i < 2; i++) {
        int f = tid + 128 * i;
        *(float4*)&Bs[0][f >> 4][(f & 15) * 4] = breg[i];
    }
    __syncthreads();

    for (int k0 = 0; k0 < nk; k0++) {
        const int buf = k0 & 1;
        if (k0 + 1 < nk) {
            const int kb = kbase + ((k0 + 1) << 4);
#pragma unroll
            for (int i = 0; i < 4; i++)
                areg[i] = *(const float4*)&A[(size_t)(bm + tid) * K + kb + i * 4];
#pragma unroll
            for (int i = 0; i < 2; i++) {
                int f = tid + 128 * i;
                breg[i] = *(const float4*)&W[(size_t)(kb + (f >> 4)) * Nc + bn + (f & 15) * 4];
            }
        }
#pragma unroll
        for (int kk = 0; kk < 16; kk++) {
            ulonglong2 a0 = *(const ulonglong2*)&Ad[buf][kk][ty * 16];
            ulonglong2 a1 = *(const ulonglong2*)&Ad[buf][kk][ty * 16 + 4];
            ulonglong2 a2 = *(const ulonglong2*)&Ad[buf][kk][ty * 16 + 8];
            ulonglong2 a3 = *(const ulonglong2*)&Ad[buf][kk][ty * 16 + 12];
            ulonglong2 b0 = *(const ulonglong2*)&Bs[buf][kk][tx * 8];
            ulonglong2 b1 = *(const ulonglong2*)&Bs[buf][kk][tx * 8 + 4];
            u64 av[8] = {a0.x, a0.y, a1.x, a1.y, a2.x, a2.y, a3.x, a3.y};
            u64 bv[4] = {b0.x, b0.y, b1.x, b1.y};
#pragma unroll
            for (int m = 0; m < 8; m++) {
                ffma2(acc[m][0], av[m], bv[0]);
                ffma2(acc[m][1], av[m], bv[1]);
                ffma2(acc[m][2], av[m], bv[2]);
                ffma2(acc[m][3], av[m], bv[3]);
            }
        }
        if (k0 + 1 < nk) {
            const int nb = buf ^ 1;
#pragma unroll
            for (int i = 0; i < 4; i++) {
                *(float2*)&Ad[nb][i * 4 + 0][2 * tid] = make_float2(areg[i].x, areg[i].x);
                *(float2*)&Ad[nb][i * 4 + 1][2 * tid] = make_float2(areg[i].y, areg[i].y);
                *(float2*)&Ad[nb][i * 4 + 2][2 * tid] = make_float2(areg[i].z, areg[i].z);
                *(float2*)&Ad[nb][i * 4 + 3][2 * tid] = make_float2(areg[i].w, areg[i].w);
            }
#pragma unroll
            for (int i = 0; i < 2; i++) {
                int f = tid + 128 * i;
                *(float4*)&Bs[nb][f >> 4][(f & 15) * 4] = breg[i];
            }
        }
        __syncthreads();
    }

    float c[8][8];
#pragma unroll
    for (int m = 0; m < 8; m++) {
        unpack2(acc[m][0], c[m][0], c[m][1]);
        unpack2(acc[m][1], c[m][2], c[m][3]);
        unpack2(acc[m][2], c[m][4], c[m][5]);
        unpack2(acc[m][3], c[m][6], c[m][7]);
    }

    if (S > 1) {
        const size_t plane = (size_t)M * Nc;
#pragma unroll
        for (int m = 0; m < 8; m++) {
            int row = bm + ty * 8 + m;
            float* p = &part[z * plane + (size_t)row * Nc + bn + tx * 8];
            *(float4*)p       = make_float4(c[m][0], c[m][1], c[m][2], c[m][3]);
            *(float4*)(p + 4) = make_float4(c[m][4], c[m][5], c[m][6], c[m][7]);
        }
        return;
    }

    float bv8[8] = {0.f, 0.f, 0.f, 0.f, 0.f, 0.f, 0.f, 0.f};
    if (bias) {
        float4 b0 = *(const float4*)&bias[bn + tx * 8];
        float4 b1 = *(const float4*)&bias[bn + tx * 8 + 4];
        bv8[0] = b0.x; bv8[1] = b0.y; bv8[2] = b0.z; bv8[3] = b0.w;
        bv8[4] = b1.x; bv8[5] = b1.y; bv8[6] = b1.z; bv8[7] = b1.w;
    }

    if (mode == 2) {
#pragma unroll
        for (int p = 0; p < 4; p++) {
            float v[8];
#pragma unroll
            for (int n = 0; n < 8; n++)
                v[n] = 0.5f * (c[2 * p][n] + c[2 * p + 1][n]) + bv8[n];
            int pr = (bm >> 1) + ty * 4 + p;
            float* o = &C[(size_t)pr * Nc + bn + tx * 8];
            *(float4*)o       = make_float4(v[0], v[1], v[2], v[3]);
            *(float4*)(o + 4) = make_float4(v[4], v[5], v[6], v[7]);
        }
    } else {
#pragma unroll
        for (int m = 0; m < 8; m++) {
            float v[8];
#pragma unroll
            for (int n = 0; n < 8; n++) {
                v[n] = c[m][n] + bv8[n];
                if (mode == 1) v[n] = fmaxf(v[n], 0.f);
            }
            int row = bm + ty * 8 + m;
            float* o = &C[(size_t)row * Nc + bn + tx * 8];
            *(float4*)o       = make_float4(v[0], v[1], v[2], v[3]);
            *(float4*)(o + 4) = make_float4(v[4], v[5], v[6], v[7]);
        }
    }
}

// ---------------------------------------------------------------------------
// Split-K reduction
// ---------------------------------------------------------------------------
__global__ void reduce_k(const float* __restrict__ part, const float* __restrict__ bias,
                         float* __restrict__ C, int M, int Nc, int S, int mode)
{
    int idx = blockIdx.x * blockDim.x + threadIdx.x;
    const int nc4 = Nc >> 2;
    const int rows = (mode == 2) ? (M >> 1) : M;
    if (idx >= rows * nc4) return;
    int r = idx / nc4, c4 = idx - r * nc4;
    const size_t plane = (size_t)M * Nc;

    float4 s = make_float4(0.f, 0.f, 0.f, 0.f);
    if (mode == 2) {
        for (int z = 0; z < S; z++) {
            float4 a = *(const float4*)&part[z * plane + (size_t)(2 * r)     * Nc + c4 * 4];
            float4 b = *(const float4*)&part[z * plane + (size_t)(2 * r + 1) * Nc + c4 * 4];
            s.x += a.x + b.x; s.y += a.y + b.y; s.z += a.z + b.z; s.w += a.w + b.w;
        }
        s.x *= 0.5f; s.y *= 0.5f; s.z *= 0.5f; s.w *= 0.5f;
    } else {
        for (int z = 0; z < S; z++) {
            float4 a = *(const float4*)&part[z * plane + (size_t)r * Nc + c4 * 4];
            s.x += a.x; s.y += a.y; s.z += a.z; s.w += a.w;
        }
    }
    float4 bb = make_float4(0.f, 0.f, 0.f, 0.f);
    if (bias) bb = ((const float4*)bias)[c4];
    s.x += bb.x; s.y += bb.y; s.z += bb.z; s.w += bb.w;
    if (mode == 1) {
        s.x = fmaxf(s.x, 0.f); s.y = fmaxf(s.y, 0.f);
        s.z = fmaxf(s.z, 0.f); s.w = fmaxf(s.w, 0.f);
    }
    *(float4*)&C[(size_t)r * Nc + c4 * 4] = s;
}

// ---------------------------------------------------------------------------
// Multi-head attention: qkv [B, Nl, 3*DIM] -> out [B, Nl, DIM]
// grid (B*NH, Nl/32), 256 threads. Each warp processes 4 query rows at once:
// K[j] loaded once per j feeds 4 rows (q broadcast); probs staged as (p,p)
// pairs for 4 rows so AV does 2 V-trans + 2 p-broadcasts per j for 4 rows.
// ---------------------------------------------------------------------------
__global__ void __launch_bounds__(256)
attn_k(const float* __restrict__ qkv, float* __restrict__ out, int Nl)
{
    extern __shared__ float sm[];
    float* Ks  = sm;                    // Nl*68
    float* Vs  = Ks + Nl * 68;          // Nl*68
    float* qs  = Vs + Nl * 68;          // 8 warps * 4 rows * 68
    float* psd = qs + 8 * 4 * 68;       // 8 warps * Nl * 8  ((p,p) x 4 rows)

    const int b = blockIdx.x >> 3, h = blockIdx.x & 7;
    const float* base = qkv + (size_t)b * Nl * (3 * DIM);
    const int tid = threadIdx.x, warp = tid >> 5, lane = tid & 31;

    for (int idx = tid; idx < Nl * 16; idx += 256) {
        int n = idx >> 4, dv = idx & 15;
        const float* rowp = base + (size_t)n * (3 * DIM) + h * 64 + dv * 4;
        *(float4*)&Ks[n * 68 + dv * 4] = *(const float4*)(rowp + DIM);
        *(float4*)&Vs[n * 68 + dv * 4] = *(const float4*)(rowp + 2 * DIM);
    }
    __syncthreads();

    const int jcnt = Nl >> 5;                  // <= 8
    const int row0 = blockIdx.y * 32 + warp * 4;

    // load q for 4 rows into qs[warp]
#pragma unroll
    for (int i = 0; i < 2; i++) {
        int idx = lane + 32 * i;               // 0..63
        int r = idx >> 4, c = idx & 15;
        *(float4*)&qs[(warp * 4 + r) * 68 + c * 4] =
            *(const float4*)&base[(size_t)(row0 + r) * (3 * DIM) + h * 64 + c * 4];
    }
    __syncwarp();

    // ---- QK: scores for 4 rows ----
    float sv[4][8];
    for (int t = 0; t < jcnt; t++) {
        int j = t * 32 + lane;
        const ulonglong2* kr = (const ulonglong2*)&Ks[j * 68];
        u64 a0[2] = {0ull, 0ull}, a1[2] = {0ull, 0ull};
        u64 a2[2] = {0ull, 0ull}, a3[2] = {0ull, 0ull};
#pragma unroll
        for (int c = 0; c < 16; c++) {
            ulonglong2 k = kr[c];
            ulonglong2 q0 = *(const ulonglong2*)&qs[(warp * 4 + 0) * 68 + c * 4];
            ulonglong2 q1 = *(const ulonglong2*)&qs[(warp * 4 + 1) * 68 + c * 4];
            ulonglong2 q2 = *(const ulonglong2*)&qs[(warp * 4 + 2) * 68 + c * 4];
            ulonglong2 q3 = *(const ulonglong2*)&qs[(warp * 4 + 3) * 68 + c * 4];
            ffma2(a0[0], q0.x, k.x); ffma2(a0[1], q0.y, k.y);
            ffma2(a1[0], q1.x, k.x); ffma2(a1[1], q1.y, k.y);
            ffma2(a2[0], q2.x, k.x); ffma2(a2[1], q2.y, k.y);
            ffma2(a3[0], q3.x, k.x); ffma2(a3[1], q3.y, k.y);
        }
        float x0, x1, x2, x3;
        unpack2(a0[0], x0, x1); unpack2(a0[1], x2, x3);
        sv[0][t] = (x0 + x1 + x2 + x3) * 0.125f;
        unpack2(a1[0], x0, x1); unpack2(a1[1], x2, x3);
        sv[1][t] = (x0 + x1 + x2 + x3) * 0.125f;
        unpack2(a2[0], x0, x1); unpack2(a2[1], x2, x3);
        sv[2][t] = (x0 + x1 + x2 + x3) * 0.125f;
        unpack2(a3[0], x0, x1); unpack2(a3[1], x2, x3);
        sv[3][t] = (x0 + x1 + x2 + x3) * 0.125f;
    }

    // ---- softmax per row + stage probs ----
    float inv[4];
#pragma unroll
    for (int r = 0; r < 4; r++) {
        float mx = -1e30f;
        for (int t = 0; t < jcnt; t++) mx = fmaxf(mx, sv[r][t]);
#pragma unroll
        for (int o = 16; o; o >>= 1) mx = fmaxf(mx, __shfl_xor_sync(0xffffffffu, mx, o));
        float sum = 0.f;
        for (int t = 0; t < jcnt; t++) { float e = expf(sv[r][t] - mx); sv[r][t] = e; sum += e; }
#pragma unroll
        for (int o = 16; o; o >>= 1) sum += __shfl_xor_sync(0xffffffffu, sum, o);
        inv[r] = 1.f / sum;
    }
    float* pw = &psd[warp * Nl * 8];
    for (int t = 0; t < jcnt; t++) {
        int j = t * 32 + lane;
#pragma unroll
        for (int r = 0; r < 4; r++) {
            float p = sv[r][t] * inv[r];
            *(float2*)&pw[j * 8 + 2 * r] = make_float2(p, p);
        }
    }
    __syncwarp();

    // ---- AV: 4 rows at once, V loaded once per j ----
    u64 av[4][2];
#pragma unroll
    for (int r = 0; r < 4; r++) { av[r][0] = 0ull; av[r][1] = 0ull; }
    for (int j = 0; j < Nl; j += 2) {
        u64 v0 = *(const u64*)&Vs[(j)     * 68 + 2 * lane];
        u64 v1 = *(const u64*)&Vs[(j + 1) * 68 + 2 * lane];
        ulonglong2 pA = *(const ulonglong2*)&pw[j * 8];          // rows 0,1
        ulonglong2 pB = *(const ulonglong2*)&pw[j * 8 + 4];      // rows 2,3
        ulonglong2 pC = *(const ulonglong2*)&pw[(j + 1) * 8];
        ulonglong2 pD = *(const ulonglong2*)&pw[(j + 1) * 8 + 4];
        ffma2(av[0][0], pA.x, v0); ffma2(av[1][0], pA.y, v0);
        ffma2(av[2][0], pB.x, v0); ffma2(av[3][0], pB.y, v0);
        ffma2(av[0][1], pC.x, v1); ffma2(av[1][1], pC.y, v1);
        ffma2(av[2][1], pD.x, v1); ffma2(av[3][1], pD.y, v1);
    }
#pragma unroll
    for (int r = 0; r < 4; r++) {
        float l0, h0, l1, h1;
        unpack2(av[r][0], l0, h0);
        unpack2(av[r][1], l1, h1);
        *(float2*)&out[((size_t)b * Nl + row0 + r) * DIM + h * 64 + 2 * lane] =
            make_float2(l0 + l1, h0 + h1);
    }
}

// ---------------------------------------------------------------------------
// Upsample + concat (float4)
// ---------------------------------------------------------------------------
__global__ void concat_k(const float* __restrict__ l0, const float* __restrict__ l1,
                         const float* __restrict__ l2, float* __restrict__ cat)
{
    int idx4 = blockIdx.x * blockDim.x + threadIdx.x;
    const int total4 = BB * NNODE * 3 * DIM / 4;
    if (idx4 >= total4) return;
    int c4 = idx4 % (3 * DIM / 4);
    int n  = (idx4 / (3 * DIM / 4)) % NNODE;
    int b  = idx4 / ((3 * DIM / 4) * NNODE);
    int col = c4 * 4, l = col >> 9, d = col & 511;
    const float* src = (l == 0) ? l0 : (l == 1) ? l1 : l2;
    int Nl = NNODE >> l;
    ((float4*)cat)[idx4] = *(const float4*)&src[((size_t)b * Nl + (n >> l)) * DIM + d];
}

// ---------------------------------------------------------------------------
// LayerNorm over last dim (512)
// ---------------------------------------------------------------------------
__global__ void ln_k(const float* __restrict__ in, const float* __restrict__ g,
                     const float* __restrict__ bta, float* __restrict__ out)
{
    const int row = blockIdx.x, t = threadIdx.x;
    const int warp = t >> 5, lane = t & 31;
    float4 v = ((const float4*)(in + (size_t)row * DIM))[t];
    __shared__ float red[4];

    float s = v.x + v.y + v.z + v.w;
#pragma unroll
    for (int o = 16; o; o >>= 1) s += __shfl_xor_sync(0xffffffffu, s, o);
    if (lane == 0) red[warp] = s;
    __syncthreads();
    float mean = (red[0] + red[1] + red[2] + red[3]) * (1.f / DIM);
    __syncthreads();

    float dx = v.x - mean, dy = v.y - mean, dz = v.z - mean, dw = v.w - mean;
    float s2 = dx * dx + dy * dy + dz * dz + dw * dw;
#pragma unroll
    for (int o = 16; o; o >>= 1) s2 += __shfl_xor_sync(0xffffffffu, s2, o);
    if (lane == 0) red[warp] = s2;
    __syncthreads();
    float var = (red[0] + red[1] + red[2] + red[3]) * (1.f / DIM);
    float inv = 1.f / sqrtf(var + 1e-5f);

    float4 gv = ((const float4*)g)[t];
    float4 bv = ((const float4*)bta)[t];
    float4 r;
    r.x = dx * inv * gv.x + bv.x;
    r.y = dy * inv * gv.y + bv.y;
    r.z = dz * inv * gv.z + bv.z;
    r.w = dw * inv * gv.w + bv.w;
    ((float4*)(out + (size_t)row * DIM))[t] = r;
}

// ---------------------------------------------------------------------------
// Repack We1[1024,512] -> wef[512,1024] (hi|hj column blocks) + fused bias
// ---------------------------------------------------------------------------
__global__ void repack_k(const float* __restrict__ We1, const float* __restrict__ be1,
                         float* __restrict__ wef, float* __restrict__ bef)
{
    int idx = blockIdx.x * blockDim.x + threadIdx.x;
    if (idx < DIM * 2 * DIM) {
        int k = idx >> 10, n = idx & 1023;
        wef[idx] = (n < DIM) ? We1[(size_t)k * DIM + n]
                             : We1[(size_t)(DIM + k) * DIM + (n - DIM)];
    }
    if (idx < 2 * DIM) bef[idx] = (idx < DIM) ? 0.f : be1[idx - DIM];
}

// ---------------------------------------------------------------------------
// Edge scores from merged ef buffer (row stride 1024: [hi | hj]).
// ---------------------------------------------------------------------------
__global__ void scores_k(const float* __restrict__ ef, const float* __restrict__ w2,
                         float* __restrict__ sc)
{
    __shared__ float His[16][68];
    __shared__ float Hjs[16][36];
    __shared__ float W2s[16];
    const int b = blockIdx.z;
    const int i0 = blockIdx.y * 64, j0 = blockIdx.x * 32;
    const int tid = threadIdx.x;
    const int tx = tid & 15, ty = tid >> 4;
    const float* hib = ef + ((size_t)b * NNODE + i0) * (2 * DIM);
    const float* hjb = ef + ((size_t)b * NNODE + j0) * (2 * DIM) + DIM;

    float acc[4][2];
#pragma unroll
    for (int i = 0; i < 4; i++) { acc[i][0] = 0.f; acc[i][1] = 0.f; }

    const int ir = tid >> 2, ic = tid & 3;
    const int jr = tid >> 3, jc = tid & 7;

    for (int k0 = 0; k0 < DIM; k0 += 16) {
        float4 a = *(const float4*)&hib[(size_t)ir * (2 * DIM) + k0 + ic * 4];
        His[ic * 4 + 0][ir] = a.x; His[ic * 4 + 1][ir] = a.y;
        His[ic * 4 + 2][ir] = a.z; His[ic * 4 + 3][ir] = a.w;
        float2 c = *(const float2*)&hjb[(size_t)jr * (2 * DIM) + k0 + jc * 2];
        Hjs[jc * 2 + 0][jr] = c.x; Hjs[jc * 2 + 1][jr] = c.y;
        if (tid < 16) W2s[tid] = w2[k0 + tid];
        __syncthreads();
#pragma unroll
        for (int kk = 0; kk < 16; kk++) {
            float4 h4 = *(const float4*)&His[kk][ty * 4];
            float2 j2 = *(const float2*)&Hjs[kk][tx * 2];
            float w = W2s[kk];
            float hv[4] = {h4.x, h4.y, h4.z, h4.w};
#pragma unroll
            for (int i = 0; i < 4; i++) {
                acc[i][0] += fmaxf(hv[i] + j2.x, 0.f) * w;
                acc[i][1] += fmaxf(hv[i] + j2.y, 0.f) * w;
            }
        }
        __syncthreads();
    }

#pragma unroll
    for (int i = 0; i < 4; i++) {
        int gi = i0 + ty * 4 + i;
#pragma unroll
        for (int j = 0; j < 2; j++) {
            int gj = j0 + tx * 2 + j;
            sc[((size_t)b * NNODE + gi) * NNODE + gj] = (gi == gj) ? -1e30f : acc[i][j];
        }
    }
}

// ---------------------------------------------------------------------------
// Top-k (k=25) per row, warp per row; zeroes its row first.
// ---------------------------------------------------------------------------
__global__ void topk_k(const float* __restrict__ sc, float* __restrict__ adj)
{
    const int warp = threadIdx.x >> 5, lane = threadIdx.x & 31;
    const int row = blockIdx.x * 8 + warp;
    const float* s = sc + (size_t)row * NNODE;
    float v[8];
#pragma unroll
    for (int t = 0; t < 8; t++) v[t] = s[t * 32 + lane];
    float* arow = adj + (size_t)row * NNODE;
#pragma unroll
    for (int t = 0; t < 8; t++) arow[t * 32 + lane] = 0.f;
    __syncwarp();

    for (int it = 0; it < KSP; it++) {
        float bv = -3e38f; int bi = 0;
#pragma unroll
        for (int t = 0; t < 8; t++) {
            int j = t * 32 + lane;
            if (v[t] > bv) { bv = v[t]; bi = j; }
        }
#pragma unroll
        for (int o = 16; o; o >>= 1) {
            float ov = __shfl_xor_sync(0xffffffffu, bv, o);
            int   oi = __shfl_xor_sync(0xffffffffu, bi, o);
            if (ov > bv || (ov == bv && oi < bi)) { bv = ov; bi = oi; }
        }
        if (lane == (bi & 31)) v[bi >> 5] = -3e38f;
        if (lane == 0) arow[bi] = 1.0f;
        __syncwarp();
    }
}

// ---------------------------------------------------------------------------
// Host orchestration
// ---------------------------------------------------------------------------
static float* symaddr(const void* s)
{
    void* p = nullptr;
    cudaGetSymbolAddress(&p, s);
    return (float*)p;
}

static float* s_part = nullptr;

static void gemm(const float* A, const float* W, const float* bias, float* C,
                 int M, int K, int Nc, int mode, int S)
{
    sgemm_k<<<dim3(Nc / 64, M / 128, S), 128>>>(A, W, bias, C, M, K, Nc, mode, s_part);
    if (S > 1) {
        int rows = (mode == 2) ? M / 2 : M;
        int total = rows * (Nc / 4);
        reduce_k<<<(total + 255) / 256, 256>>>(s_part, bias, C, M, Nc, S, mode);
    }
}

static void attn(const float* qkv, float* out, int Nl)
{
    size_t smem = (size_t)(Nl * 68 * 2 + 8 * 4 * 68 + 8 * Nl * 8) * sizeof(float);
    attn_k<<<dim3(BB * NH, Nl / 32), 256, smem>>>(qkv, out, Nl);
}

extern "C" void kernel_launch(void* const* d_in, const int* in_sizes, int n_in,
                              void* d_out, int out_size)
{
    const float* x      = (const float*)d_in[0];
    const float* Wqkv   = (const float*)d_in[2];
    const float* bqkv   = (const float*)d_in[3];
    const float* Wo     = (const float*)d_in[4];
    const float* bo     = (const float*)d_in[5];
    const float* Wp1    = (const float*)d_in[6];
    const float* bp1    = (const float*)d_in[7];
    const float* Wp2    = (const float*)d_in[8];
    const float* bp2    = (const float*)d_in[9];
    const float* Wfuse  = (const float*)d_in[10];
    const float* bfuse  = (const float*)d_in[11];
    const float* ln_g   = (const float*)d_in[12];
    const float* ln_b   = (const float*)d_in[13];
    const float* We1    = (const float*)d_in[14];
    const float* be1    = (const float*)d_in[15];
    const float* We2    = (const float*)d_in[16];
    const float* Ws_qkv = (const float*)d_in[18];
    const float* bs_qkv = (const float*)d_in[19];
    const float* Ws_o   = (const float*)d_in[20];
    const float* bs_o   = (const float*)d_in[21];

    float* out_att = (float*)d_out;                      // [B,N,D]
    float* out_adj = out_att + (size_t)BB * NNODE * DIM; // [B,N,N]

    float* cur  = symaddr(g_cur);
    float* qkv  = symaddr(g_qkv);
    float* atto = symaddr(g_atto);
    float* lvl0 = symaddr(g_lvl0);
    float* lvl1 = symaddr(g_lvl1);
    float* lvl2 = symaddr(g_lvl2);
    float* t1   = symaddr(g_t1);
    float* pbuf = symaddr(g_p);
    float* cat  = symaddr(g_cat);
    float* hier = symaddr(g_hier);
    float* ef   = symaddr(g_ef);
    float* wef  = symaddr(g_wef);
    float* bef  = symaddr(g_bef);
    float* sc   = symaddr(g_sc);
    s_part      = symaddr(g_part);

    cudaFuncSetAttribute(attn_k, cudaFuncAttributeMaxDynamicSharedMemorySize, 220000);

    float* lvls[3] = {lvl0, lvl1, lvl2};
    const float* curp = x;

    // repack We1 early (independent of everything else)
    repack_k<<<(DIM * 2 * DIM + 255) / 256, 256>>>(We1, be1, wef, bef);

    // split factors tuned for 128-row tiles: grid >= ~256 CTAs, K/S mult of 16
    const int qkvS[3] = {2, 4, 8};
    const int woS [3] = {4, 8, 8};
    const int wp1S[3] = {8, 16, 0};
    const int wp2S[3] = {4, 8, 0};

    for (int l = 0; l < 3; l++) {
        const int Nl = NNODE >> l;
        const int M  = BB * Nl;
        gemm(curp, Wqkv + (size_t)l * DIM * 3 * DIM, bqkv + (size_t)l * 3 * DIM,
             qkv, M, DIM, 3 * DIM, 0, qkvS[l]);
        attn(qkv, atto, Nl);
        gemm(atto, Wo + (size_t)l * DIM * DIM, bo + (size_t)l * DIM,
             lvls[l], M, DIM, DIM, 0, woS[l]);
        if (l < 2) {
            gemm(lvls[l], Wp1 + (size_t)l * DIM * (DIM / 2), bp1 + (size_t)l * (DIM / 2),
                 t1, M, DIM, DIM / 2, 1, wp1S[l]);
            gemm(t1, Wp2 + (size_t)l * (DIM / 2) * DIM, bp2 + (size_t)l * DIM,
                 cur, M, DIM / 2, DIM, 2, wp2S[l]);
            curp = cur;
        }
    }

    // fuse: concat upsampled levels -> GEMM(relu) -> LayerNorm
    {
        const int total4 = BB * NNODE * 3 * DIM / 4;
        concat_k<<<(total4 + 255) / 256, 256>>>(lvl0, lvl1, lvl2, cat);
        gemm(cat, Wfuse, bfuse, pbuf, BB * NNODE, 3 * DIM, DIM, 1, 4);
        ln_k<<<BB * NNODE, 128>>>(pbuf, ln_g, ln_b, hier);
    }

    // sparse edge scoring + top-k (merged hi|hj GEMM)
    {
        gemm(hier, wef, bef, ef, BB * NNODE, DIM, 2 * DIM, 0, 2);
        scores_k<<<dim3(NNODE / 32, NNODE / 64, BB), 256>>>(ef, We2, sc);
        topk_k<<<BB * NNODE / 8, 256>>>(sc, out_adj);
    }

    // final MHA on hier -> attended output
    {
        const int M = BB * NNODE;
        gemm(hier, Ws_qkv, bs_qkv, qkv, M, DIM, 3 * DIM, 0, 2);
        attn(qkv, atto, NNODE);
        gemm(atto, Ws_o, bs_o, out_att, M, DIM, DIM, 0, 4);
    }
}